// round 15
// baseline (speedup 1.0000x reference)
#include <cuda_runtime.h>
#include <cuda_fp16.h>
#include <cstddef>

#define NN   50000
#define NE   400000
#define NLE  3200000
#define F    32
#define SCAN_B 1024
#define SBG   ((NN + SCAN_B - 1) / SCAN_B)   // 49
#define SBL   ((NE + SCAN_B - 1) / SCAN_B)   // 391

typedef unsigned long long u64;

// ---------------- scratch (device globals) ----------------
__device__ float d_zg0[NN * F];
__device__ float d_zg1[NN * F];
__device__ float d_zg2[NN * F];
__device__ float d_zgt[NN * F];
__device__ float d_pmy[NN * F];
__device__ uint4 d_zl0[NE * F / 8];
__device__ uint4 d_zl1[NE * F / 8];
__device__ uint4 d_zl2[NE * F / 8];
__device__ uint4 d_zlt[NE * F / 8];
__device__ float d_stats[128];

__device__ int d_cnt[NN + NE];
__device__ int d_incl[NN + NE];
__device__ int d_off[(NN + 1) + (NE + 1)];
__device__ int d_rank[NE + NLE];
__device__ int d_csr_src_g[NE];
__device__ int d_csr_eid_g[NE];
__device__ int d_csr_lg[NLE];
__device__ int d_bsum[1024];

// ---------------- helpers ----------------
__device__ __forceinline__ u64 pack2(float a, float b) {
    u64 r; asm("mov.b64 %0, {%1, %2};" : "=l"(r) : "f"(a), "f"(b)); return r;
}
__device__ __forceinline__ void unpack2(u64 v, float& a, float& b) {
    asm("mov.b64 {%0, %1}, %2;" : "=f"(a), "=f"(b) : "l"(v));
}
__device__ __forceinline__ u64 fma2(u64 a, u64 b, u64 c) {
    u64 d; asm("fma.rn.f32x2 %0, %1, %2, %3;" : "=l"(d) : "l"(a), "l"(b), "l"(c)); return d;
}
__device__ __forceinline__ unsigned int pack_h2(float a, float b) {
    __half2 h = __floats2half2_rn(a, b);
    return *(unsigned int*)&h;
}
__device__ __forceinline__ void h2_acc(float& a, float& b, unsigned int u) {
    __half2 h = *(__half2*)&u;
    float2 f = __half22float2(h);
    a += f.x; b += f.y;
}

// ================= CSR build: 4 edges/thread, int4 IO =================
__global__ void hist_both_kernel(const int* __restrict__ g_dst, const int* __restrict__ lg_dst,
                                 int* __restrict__ cnt, int* __restrict__ rank,
                                 float* __restrict__ st) {
    if (blockIdx.x == 0 && threadIdx.x < 128) st[threadIdx.x] = 0.f;
    int t = blockIdx.x * blockDim.x + threadIdx.x;
    if (t < NE / 4) {
        int4 d = __ldg((const int4*)g_dst + t);
        int4 r;
        r.x = atomicAdd(&cnt[d.x], 1);
        r.y = atomicAdd(&cnt[d.y], 1);
        r.z = atomicAdd(&cnt[d.z], 1);
        r.w = atomicAdd(&cnt[d.w], 1);
        __stcs((int4*)rank + t, r);
    } else if (t < NE / 4 + NLE / 4) {
        int i = t - NE / 4;
        int4 d = __ldg((const int4*)lg_dst + i);
        int4 r;
        r.x = atomicAdd(&cnt[NN + d.x], 1);
        r.y = atomicAdd(&cnt[NN + d.y], 1);
        r.z = atomicAdd(&cnt[NN + d.z], 1);
        r.w = atomicAdd(&cnt[NN + d.w], 1);
        __stcs((int4*)(rank + NE) + i, r);
    }
}

__global__ void scan_block_kernel(const int* __restrict__ cnt, int* __restrict__ incl,
                                  int* __restrict__ bsum) {
    int b = blockIdx.x;
    const int* c; int* in; int n; int* bs; int rel;
    if (b < SBG) { c = cnt;      in = incl;      n = NN; bs = bsum;       rel = b; }
    else         { c = cnt + NN; in = incl + NN; n = NE; bs = bsum + 512; rel = b - SBG; }
    int tid = threadIdx.x;
    int lane = tid & 31, wid = tid >> 5;
    int i = rel * SCAN_B + tid;
    int v = (i < n) ? c[i] : 0;
    int sv = v;
#pragma unroll
    for (int o = 1; o < 32; o <<= 1) {
        int t2 = __shfl_up_sync(~0u, sv, o);
        if (lane >= o) sv += t2;
    }
    __shared__ int ws[32];
    if (lane == 31) ws[wid] = sv;
    __syncthreads();
    if (wid == 0) {
        int w = ws[lane];
#pragma unroll
        for (int o = 1; o < 32; o <<= 1) {
            int t2 = __shfl_up_sync(~0u, w, o);
            if (lane >= o) w += t2;
        }
        ws[lane] = w;
    }
    __syncthreads();
    int inc = sv + (wid ? ws[wid - 1] : 0);
    if (i < n) in[i] = inc;
    if (tid == SCAN_B - 1) bs[rel] = inc;
}

__global__ void scan_add_kernel(const int* __restrict__ incl, int* __restrict__ cnt,
                                const int* __restrict__ bsum, int* __restrict__ off) {
    int b = blockIdx.x;
    const int* in; int* c; int n; const int* bs; int rel; int* o_;
    if (b < SBG) { in = incl;      c = cnt;      n = NN; bs = bsum;       rel = b;       o_ = off; }
    else         { in = incl + NN; c = cnt + NN; n = NE; bs = bsum + 512; rel = b - SBG; o_ = off + NN + 1; }
    __shared__ int red[SCAN_B];
    int t = threadIdx.x;
    red[t] = (t < rel) ? bs[t] : 0;
    __syncthreads();
#pragma unroll
    for (int o = SCAN_B / 2; o > 0; o >>= 1) {
        if (t < o) red[t] += red[t + o];
        __syncthreads();
    }
    int prefix = red[0];
    int i = rel * SCAN_B + t;
    if (i < n) {
        o_[i + 1] = in[i] + prefix;
        c[i] = 0;
        if (i == 0) o_[0] = 0;
    }
}

__global__ void fill_both_kernel(const int* __restrict__ g_src, const int* __restrict__ g_dst,
                                 const int* __restrict__ lg_src, const int* __restrict__ lg_dst,
                                 const int* __restrict__ off_g, const int* __restrict__ off_lg,
                                 const int* __restrict__ rank,
                                 int* __restrict__ csr_src_g, int* __restrict__ csr_eid_g,
                                 int* __restrict__ csr_lg) {
    int t = blockIdx.x * blockDim.x + threadIdx.x;
    if (t < NE / 4) {
        int4 d  = __ldg((const int4*)g_dst + t);
        int4 rk = __ldcs((const int4*)rank + t);
        int4 s  = __ldg((const int4*)g_src + t);
        int e = 4 * t;
        int p0 = __ldg(off_g + d.x) + rk.x;
        int p1 = __ldg(off_g + d.y) + rk.y;
        int p2 = __ldg(off_g + d.z) + rk.z;
        int p3 = __ldg(off_g + d.w) + rk.w;
        __stcs(csr_src_g + p0, s.x); __stcs(csr_eid_g + p0, e);
        __stcs(csr_src_g + p1, s.y); __stcs(csr_eid_g + p1, e + 1);
        __stcs(csr_src_g + p2, s.z); __stcs(csr_eid_g + p2, e + 2);
        __stcs(csr_src_g + p3, s.w); __stcs(csr_eid_g + p3, e + 3);
    } else if (t < NE / 4 + NLE / 4) {
        int i = t - NE / 4;
        int4 d  = __ldg((const int4*)lg_dst + i);
        int4 rk = __ldcs((const int4*)(rank + NE) + i);
        int4 s  = __ldg((const int4*)lg_src + i);
        __stcs(csr_lg + __ldg(off_lg + d.x) + rk.x, s.x);
        __stcs(csr_lg + __ldg(off_lg + d.y) + rk.y, s.y);
        __stcs(csr_lg + __ldg(off_lg + d.z) + rk.z, s.z);
        __stcs(csr_lg + __ldg(off_lg + d.w) + rk.w, s.w);
    }
}

// ================= pull SpMM =================
__device__ __forceinline__ void pull_f32_f32(const float* __restrict__ z, const int* __restrict__ off,
                                             const int* __restrict__ idx, float* __restrict__ out,
                                             int r, int lane, unsigned m8) {
    int b = __ldg(off + r), e = __ldg(off + r + 1);
    float4 acc = make_float4(0.f, 0.f, 0.f, 0.f);
    int i = b;
    for (; i + 3 < e; i += 4) {
        int v = __ldg(idx + i + (lane & 3));
        int s0 = __shfl_sync(m8, v, 0, 8);
        int s1 = __shfl_sync(m8, v, 1, 8);
        int s2 = __shfl_sync(m8, v, 2, 8);
        int s3 = __shfl_sync(m8, v, 3, 8);
        float4 v0 = *((const float4*)(z + (size_t)s0 * F) + lane);
        float4 v1 = *((const float4*)(z + (size_t)s1 * F) + lane);
        float4 v2 = *((const float4*)(z + (size_t)s2 * F) + lane);
        float4 v3 = *((const float4*)(z + (size_t)s3 * F) + lane);
        acc.x += (v0.x + v1.x) + (v2.x + v3.x);
        acc.y += (v0.y + v1.y) + (v2.y + v3.y);
        acc.z += (v0.z + v1.z) + (v2.z + v3.z);
        acc.w += (v0.w + v1.w) + (v2.w + v3.w);
    }
    for (; i < e; i++) {
        int s0 = __ldg(idx + i);
        float4 v0 = *((const float4*)(z + (size_t)s0 * F) + lane);
        acc.x += v0.x; acc.y += v0.y; acc.z += v0.z; acc.w += v0.w;
    }
    __stcs((float4*)(out + (size_t)r * F) + lane, acc);
}

// dual-row fp32 -> fp16: rows 2g and 2g+1, interleaved unroll-4 loops
__device__ __forceinline__ void pull_f32_h4_dual(const float* __restrict__ z, const int* __restrict__ off,
                                                 const int* __restrict__ idx, uint4* __restrict__ out,
                                                 int g, int lane, unsigned m4) {
    int r0 = 2 * g;
    int b0 = __ldg(off + r0), e0 = __ldg(off + r0 + 1), e1 = __ldg(off + r0 + 2);
    int b1 = e0;
    float a0 = 0.f, a1 = 0.f, a2 = 0.f, a3 = 0.f, a4 = 0.f, a5 = 0.f, a6 = 0.f, a7 = 0.f;
    float c0 = 0.f, c1 = 0.f, c2 = 0.f, c3 = 0.f, c4 = 0.f, c5 = 0.f, c6 = 0.f, c7 = 0.f;
    int i0 = b0, i1 = b1;
    while (i0 + 3 < e0 && i1 + 3 < e1) {
        int va = __ldg(idx + i0 + lane);
        int vb = __ldg(idx + i1 + lane);
#pragma unroll
        for (int q = 0; q < 4; q++) {
            int sa = __shfl_sync(m4, va, q, 4);
            int sb = __shfl_sync(m4, vb, q, 4);
            const float4* pa = (const float4*)(z + (size_t)sa * F) + lane * 2;
            const float4* pb = (const float4*)(z + (size_t)sb * F) + lane * 2;
            float4 u0 = pa[0], u1 = pa[1];
            float4 w0 = pb[0], w1 = pb[1];
            a0 += u0.x; a1 += u0.y; a2 += u0.z; a3 += u0.w;
            a4 += u1.x; a5 += u1.y; a6 += u1.z; a7 += u1.w;
            c0 += w0.x; c1 += w0.y; c2 += w0.z; c3 += w0.w;
            c4 += w1.x; c5 += w1.y; c6 += w1.z; c7 += w1.w;
        }
        i0 += 4; i1 += 4;
    }
    for (; i0 + 3 < e0; i0 += 4) {
        int va = __ldg(idx + i0 + lane);
#pragma unroll
        for (int q = 0; q < 4; q++) {
            int sa = __shfl_sync(m4, va, q, 4);
            const float4* pa = (const float4*)(z + (size_t)sa * F) + lane * 2;
            float4 u0 = pa[0], u1 = pa[1];
            a0 += u0.x; a1 += u0.y; a2 += u0.z; a3 += u0.w;
            a4 += u1.x; a5 += u1.y; a6 += u1.z; a7 += u1.w;
        }
    }
    for (; i1 + 3 < e1; i1 += 4) {
        int vb = __ldg(idx + i1 + lane);
#pragma unroll
        for (int q = 0; q < 4; q++) {
            int sb = __shfl_sync(m4, vb, q, 4);
            const float4* pb = (const float4*)(z + (size_t)sb * F) + lane * 2;
            float4 w0 = pb[0], w1 = pb[1];
            c0 += w0.x; c1 += w0.y; c2 += w0.z; c3 += w0.w;
            c4 += w1.x; c5 += w1.y; c6 += w1.z; c7 += w1.w;
        }
    }
    for (; i0 < e0; i0++) {
        int sa = __ldg(idx + i0);
        const float4* pa = (const float4*)(z + (size_t)sa * F) + lane * 2;
        float4 u0 = pa[0], u1 = pa[1];
        a0 += u0.x; a1 += u0.y; a2 += u0.z; a3 += u0.w;
        a4 += u1.x; a5 += u1.y; a6 += u1.z; a7 += u1.w;
    }
    for (; i1 < e1; i1++) {
        int sb = __ldg(idx + i1);
        const float4* pb = (const float4*)(z + (size_t)sb * F) + lane * 2;
        float4 w0 = pb[0], w1 = pb[1];
        c0 += w0.x; c1 += w0.y; c2 += w0.z; c3 += w0.w;
        c4 += w1.x; c5 += w1.y; c6 += w1.z; c7 += w1.w;
    }
    uint4 o0, o1;
    o0.x = pack_h2(a0, a1); o0.y = pack_h2(a2, a3);
    o0.z = pack_h2(a4, a5); o0.w = pack_h2(a6, a7);
    o1.x = pack_h2(c0, c1); o1.y = pack_h2(c2, c3);
    o1.z = pack_h2(c4, c5); o1.w = pack_h2(c6, c7);
    __stcs(out + (size_t)r0 * 4 + lane, o0);
    __stcs(out + (size_t)(r0 + 1) * 4 + lane, o1);
}

// dual-row fp16 -> fp16
__device__ __forceinline__ void pull_h_h4_dual(const uint4* __restrict__ z, const int* __restrict__ off,
                                               const int* __restrict__ idx, uint4* __restrict__ out,
                                               int g, int lane, unsigned m4) {
    int r0 = 2 * g;
    int b0 = __ldg(off + r0), e0 = __ldg(off + r0 + 1), e1 = __ldg(off + r0 + 2);
    int b1 = e0;
    float a0 = 0.f, a1 = 0.f, a2 = 0.f, a3 = 0.f, a4 = 0.f, a5 = 0.f, a6 = 0.f, a7 = 0.f;
    float c0 = 0.f, c1 = 0.f, c2 = 0.f, c3 = 0.f, c4 = 0.f, c5 = 0.f, c6 = 0.f, c7 = 0.f;
    int i0 = b0, i1 = b1;
    while (i0 + 3 < e0 && i1 + 3 < e1) {
        int va = __ldg(idx + i0 + lane);
        int vb = __ldg(idx + i1 + lane);
#pragma unroll
        for (int q = 0; q < 4; q++) {
            int sa = __shfl_sync(m4, va, q, 4);
            int sb = __shfl_sync(m4, vb, q, 4);
            uint4 u = __ldg(z + (size_t)sa * 4 + lane);
            uint4 w = __ldg(z + (size_t)sb * 4 + lane);
            h2_acc(a0, a1, u.x); h2_acc(a2, a3, u.y); h2_acc(a4, a5, u.z); h2_acc(a6, a7, u.w);
            h2_acc(c0, c1, w.x); h2_acc(c2, c3, w.y); h2_acc(c4, c5, w.z); h2_acc(c6, c7, w.w);
        }
        i0 += 4; i1 += 4;
    }
    for (; i0 + 3 < e0; i0 += 4) {
        int va = __ldg(idx + i0 + lane);
#pragma unroll
        for (int q = 0; q < 4; q++) {
            int sa = __shfl_sync(m4, va, q, 4);
            uint4 u = __ldg(z + (size_t)sa * 4 + lane);
            h2_acc(a0, a1, u.x); h2_acc(a2, a3, u.y); h2_acc(a4, a5, u.z); h2_acc(a6, a7, u.w);
        }
    }
    for (; i1 + 3 < e1; i1 += 4) {
        int vb = __ldg(idx + i1 + lane);
#pragma unroll
        for (int q = 0; q < 4; q++) {
            int sb = __shfl_sync(m4, vb, q, 4);
            uint4 w = __ldg(z + (size_t)sb * 4 + lane);
            h2_acc(c0, c1, w.x); h2_acc(c2, c3, w.y); h2_acc(c4, c5, w.z); h2_acc(c6, c7, w.w);
        }
    }
    for (; i0 < e0; i0++) {
        uint4 u = __ldg(z + (size_t)__ldg(idx + i0) * 4 + lane);
        h2_acc(a0, a1, u.x); h2_acc(a2, a3, u.y); h2_acc(a4, a5, u.z); h2_acc(a6, a7, u.w);
    }
    for (; i1 < e1; i1++) {
        uint4 w = __ldg(z + (size_t)__ldg(idx + i1) * 4 + lane);
        h2_acc(c0, c1, w.x); h2_acc(c2, c3, w.y); h2_acc(c4, c5, w.z); h2_acc(c6, c7, w.w);
    }
    uint4 o0, o1;
    o0.x = pack_h2(a0, a1); o0.y = pack_h2(a2, a3);
    o0.z = pack_h2(a4, a5); o0.w = pack_h2(a6, a7);
    o1.x = pack_h2(c0, c1); o1.y = pack_h2(c2, c3);
    o1.z = pack_h2(c4, c5); o1.w = pack_h2(c6, c7);
    __stcs(out + (size_t)r0 * 4 + lane, o0);
    __stcs(out + (size_t)(r0 + 1) * 4 + lane, o1);
}

// mode 0: hop1 ; mode 1: hops 2-4. lg segment: NE/2 groups x 4 lanes (2 rows/group)
__global__ void hops_kernel(
    const float* __restrict__ zf, const uint4* __restrict__ zh,
    const int* __restrict__ off_lg, const int* __restrict__ csr_lg, uint4* __restrict__ o_lg,
    const float* __restrict__ zg, const int* __restrict__ off_g, const int* __restrict__ csr_g,
    float* __restrict__ o_g,
    const float* __restrict__ y3, const int* __restrict__ eid3, float* __restrict__ o3, int n3,
    int mode)
{
    long long t = (long long)blockIdx.x * blockDim.x + threadIdx.x;
    int wlane = threadIdx.x & 31;
    const long long lgT = (long long)NE * 2;   // NE/2 groups * 4 lanes
    if (t < lgT) {
        int g = (int)(t >> 2), lane = (int)(t & 3);
        unsigned m4 = 0xFu << (wlane & 28);
        if (mode == 0) pull_f32_h4_dual(zf, off_lg, csr_lg, o_lg, g, lane, m4);
        else           pull_h_h4_dual(zh, off_lg, csr_lg, o_lg, g, lane, m4);
    } else {
        long long t2 = t - lgT;
        unsigned m8 = 0xFFu << (wlane & 24);
        if (t2 < (long long)NN * 8) {
            pull_f32_f32(zg, off_g, csr_g, o_g, (int)(t2 >> 3), (int)(t2 & 7), m8);
        } else {
            long long t3 = t2 - (long long)NN * 8;
            if (t3 < (long long)n3 * 8)
                pull_f32_f32(y3, off_g, eid3, o3, (int)(t3 >> 3), (int)(t3 & 7), m8);
        }
    }
}

// ================= fused assemble (f32x2) =================
__device__ __forceinline__ void mv_acc2(u64 acc[16], const float* __restrict__ vec,
                                        float scale, const u64 (&W)[F][16], bool streaming) {
#pragma unroll 1
    for (int k4 = 0; k4 < 8; k4++) {
        float4 v = streaming ? __ldcs((const float4*)vec + k4) : *((const float4*)vec + k4);
        float c0 = v.x * scale, c1 = v.y * scale, c2 = v.z * scale, c3 = v.w * scale;
        u64 a0 = pack2(c0, c0), a1 = pack2(c1, c1), a2 = pack2(c2, c2), a3 = pack2(c3, c3);
#pragma unroll
        for (int j = 0; j < 16; j++) acc[j] = fma2(a0, W[k4 * 4 + 0][j], acc[j]);
#pragma unroll
        for (int j = 0; j < 16; j++) acc[j] = fma2(a1, W[k4 * 4 + 1][j], acc[j]);
#pragma unroll
        for (int j = 0; j < 16; j++) acc[j] = fma2(a2, W[k4 * 4 + 2][j], acc[j]);
#pragma unroll
        for (int j = 0; j < 16; j++) acc[j] = fma2(a3, W[k4 * 4 + 3][j], acc[j]);
    }
}

__device__ __forceinline__ void mv_acc2_h(u64 acc[16], const uint4* __restrict__ vec,
                                          const u64 (&W)[F][16]) {
#pragma unroll 1
    for (int q = 0; q < 4; q++) {
        uint4 u = __ldcs(vec + q);
        float f0, f1, f2, f3, f4, f5, f6, f7;
        { __half2 h = *(__half2*)&u.x; float2 f = __half22float2(h); f0 = f.x; f1 = f.y; }
        { __half2 h = *(__half2*)&u.y; float2 f = __half22float2(h); f2 = f.x; f3 = f.y; }
        { __half2 h = *(__half2*)&u.z; float2 f = __half22float2(h); f4 = f.x; f5 = f.y; }
        { __half2 h = *(__half2*)&u.w; float2 f = __half22float2(h); f6 = f.x; f7 = f.y; }
        u64 a0 = pack2(f0, f0), a1 = pack2(f1, f1), a2 = pack2(f2, f2), a3 = pack2(f3, f3);
        u64 a4 = pack2(f4, f4), a5 = pack2(f5, f5), a6 = pack2(f6, f6), a7 = pack2(f7, f7);
        int k = q * 8;
#pragma unroll
        for (int j = 0; j < 16; j++) acc[j] = fma2(a0, W[k + 0][j], acc[j]);
#pragma unroll
        for (int j = 0; j < 16; j++) acc[j] = fma2(a1, W[k + 1][j], acc[j]);
#pragma unroll
        for (int j = 0; j < 16; j++) acc[j] = fma2(a2, W[k + 2][j], acc[j]);
#pragma unroll
        for (int j = 0; j < 16; j++) acc[j] = fma2(a3, W[k + 3][j], acc[j]);
#pragma unroll
        for (int j = 0; j < 16; j++) acc[j] = fma2(a4, W[k + 4][j], acc[j]);
#pragma unroll
        for (int j = 0; j < 16; j++) acc[j] = fma2(a5, W[k + 5][j], acc[j]);
#pragma unroll
        for (int j = 0; j < 16; j++) acc[j] = fma2(a6, W[k + 6][j], acc[j]);
#pragma unroll
        for (int j = 0; j < 16; j++) acc[j] = fma2(a7, W[k + 7][j], acc[j]);
    }
}

__global__ void assemble_both_kernel(
    const float* __restrict__ xb, const float* __restrict__ xdeg, const float* __restrict__ xextra,
    const float* __restrict__ xz0, const float* __restrict__ xz1, const float* __restrict__ xz2,
    const float* __restrict__ xWm, const float* __restrict__ xbm,
    const float* __restrict__ xWl, const float* __restrict__ xbl,
    float* __restrict__ xout, int nx, int bx,
    const float* __restrict__ yb, const float* __restrict__ ydeg, const float* __restrict__ yextra,
    const int* __restrict__ gatherIdx,
    const uint4* __restrict__ yz0, const uint4* __restrict__ yz1, const uint4* __restrict__ yz2,
    const float* __restrict__ yWm, const float* __restrict__ ybm,
    const float* __restrict__ yWl, const float* __restrict__ ybl,
    float* __restrict__ yout, int ny)
{
    bool isX = (int)blockIdx.x < bx;
    const float* Wmain = isX ? xWm : yWm;
    const float* bmain = isX ? xbm : ybm;
    const float* Wlist = isX ? xWl : yWl;
    const float* blist = isX ? xbl : ybl;

    __shared__ u64 sW[6][F][16];
    __shared__ u64 sb[16];
    for (int i = threadIdx.x; i < 6 * F * 16; i += blockDim.x) {
        int m = i >> 9;
        int rem = i & 511;
        int k = rem >> 4;
        int j2 = rem & 15;
        const float* W = (m < 3) ? (Wmain + m * 1024) : (Wlist + (m - 3) * 1024);
        sW[m][k][j2] = pack2(W[(2 * j2) * 32 + k], W[(2 * j2 + 1) * 32 + k]);
    }
    if (threadIdx.x < 16) {
        int j2 = threadIdx.x;
        float b0 = 0.f, b1 = 0.f;
#pragma unroll
        for (int m = 0; m < 3; m++) {
            b0 += bmain[m * 32 + 2 * j2] + blist[m * 32 + 2 * j2];
            b1 += bmain[m * 32 + 2 * j2 + 1] + blist[m * 32 + 2 * j2 + 1];
        }
        sb[j2] = pack2(b0, b1);
    }
    __syncthreads();

    u64 acc[16];
#pragma unroll
    for (int j = 0; j < 16; j++) acc[j] = sb[j];

    float* out;
    int r;
    if (isX) {
        r = (int)blockIdx.x * blockDim.x + threadIdx.x;
        if (r >= nx) return;
        out = xout;
        size_t r32 = (size_t)r * F;
        float dg = xdeg[r];
        mv_acc2(acc, xb + r32, 1.f, sW[0], false);
        mv_acc2(acc, xb + r32, dg,  sW[1], false);
        mv_acc2(acc, xextra + r32, 1.f, sW[2], true);
        mv_acc2(acc, xz0 + r32, 1.f, sW[3], true);
        mv_acc2(acc, xz1 + r32, 1.f, sW[4], true);
        mv_acc2(acc, xz2 + r32, 1.f, sW[5], true);
    } else {
        r = ((int)blockIdx.x - bx) * blockDim.x + threadIdx.x;
        if (r >= ny) return;
        out = yout;
        size_t r32 = (size_t)r * F;
        float dg = ydeg[r];
        mv_acc2(acc, yb + r32, 1.f, sW[0], false);
        mv_acc2(acc, yb + r32, dg,  sW[1], false);
        mv_acc2(acc, yextra + (size_t)__ldg(gatherIdx + r) * F, 1.f, sW[2], false);
        mv_acc2_h(acc, yz0 + (size_t)r * 4, sW[3]);
        mv_acc2_h(acc, yz1 + (size_t)r * 4, sW[4]);
        mv_acc2_h(acc, yz2 + (size_t)r * 4, sW[5]);
    }

    float vals[F];
#pragma unroll
    for (int j = 0; j < 16; j++) unpack2(acc[j], vals[2 * j], vals[2 * j + 1]);
#pragma unroll
    for (int j = F / 2; j < F; j++) vals[j] = fmaxf(vals[j], 0.f);

    float4* op = (float4*)(out + (size_t)r * F);
#pragma unroll
    for (int j = 0; j < 8; j++)
        op[j] = make_float4(vals[4 * j], vals[4 * j + 1], vals[4 * j + 2], vals[4 * j + 3]);
}

// ================= BN stats =================
__global__ void stats_both_kernel(const float* __restrict__ vx, const float* __restrict__ vy,
                                  int gx, float* __restrict__ st) {
    bool isX = (int)blockIdx.x < gx;
    const float* v = isX ? vx : vy;
    long long nRows = isX ? NN : NE;
    float* s0 = st + (isX ? 0 : 64);
    int nb = isX ? gx : (gridDim.x - gx);
    int rb = isX ? (int)blockIdx.x : (int)blockIdx.x - gx;

    int col = threadIdx.x & 31;
    int w = threadIdx.x >> 5;
    int warpsPerBlock = blockDim.x >> 5;
    float s = 0.f, s2 = 0.f;
    for (long long r = (long long)rb * warpsPerBlock + w; r < nRows;
         r += (long long)nb * warpsPerBlock) {
        float val = v[r * F + col];
        s += val;
        s2 += val * val;
    }
    __shared__ float sm[2][8][F];
    sm[0][w][col] = s;
    sm[1][w][col] = s2;
    __syncthreads();
    if (threadIdx.x < F) {
        float a = 0.f, b = 0.f;
#pragma unroll
        for (int ww = 0; ww < 8; ww++) { a += sm[0][ww][threadIdx.x]; b += sm[1][ww][threadIdx.x]; }
        atomicAdd(&s0[threadIdx.x], a);
        atomicAdd(&s0[F + threadIdx.x], b);
    }
}

// ================= BN normalize =================
__global__ void normalize_both_kernel(float* __restrict__ vx, float* __restrict__ vy,
                                      int gx, const float* __restrict__ st,
                                      const float* __restrict__ sx, const float* __restrict__ bxx,
                                      const float* __restrict__ sy, const float* __restrict__ byy) {
    bool isX = (int)blockIdx.x < gx;
    float* v = isX ? vx : vy;
    long long nRows = isX ? NN : NE;
    const float* s0 = st + (isX ? 0 : 64);
    const float* scale = isX ? sx : sy;
    const float* bias  = isX ? bxx : byy;
    int nb = isX ? gx : (gridDim.x - gx);
    int rb = isX ? (int)blockIdx.x : (int)blockIdx.x - gx;

    __shared__ float mulc[F], addc[F];
    if (threadIdx.x < F) {
        float m = s0[threadIdx.x] / (float)nRows;
        float var = s0[F + threadIdx.x] / (float)nRows - m * m;
        float g = rsqrtf(var + 1e-5f) * scale[threadIdx.x];
        mulc[threadIdx.x] = g;
        addc[threadIdx.x] = bias[threadIdx.x] - m * g;
    }
    __syncthreads();
    int col = threadIdx.x & 31;
    int w = threadIdx.x >> 5;
    int warpsPerBlock = blockDim.x >> 5;
    for (long long r = (long long)rb * warpsPerBlock + w; r < nRows;
         r += (long long)nb * warpsPerBlock) {
        v[r * F + col] = fmaf(v[r * F + col], mulc[col], addc[col]);
    }
}

// ================= launcher =================
extern "C" void kernel_launch(void* const* d_in, const int* in_sizes, int n_in,
                              void* d_out, int out_size) {
    const float* x            = (const float*)d_in[0];
    const float* y            = (const float*)d_in[1];
    const float* deg_g        = (const float*)d_in[2];
    const float* deg_lg       = (const float*)d_in[3];
    const float* theta_main_w = (const float*)d_in[4];
    const float* theta_main_b = (const float*)d_in[5];
    const float* theta_list_w = (const float*)d_in[6];
    const float* theta_list_b = (const float*)d_in[7];
    const float* gamma_main_w = (const float*)d_in[8];
    const float* gamma_main_b = (const float*)d_in[9];
    const float* gamma_list_w = (const float*)d_in[10];
    const float* gamma_list_b = (const float*)d_in[11];
    const float* bn_x_scale   = (const float*)d_in[12];
    const float* bn_x_bias    = (const float*)d_in[13];
    const float* bn_y_scale   = (const float*)d_in[14];
    const float* bn_y_bias    = (const float*)d_in[15];
    const int*   g_src        = (const int*)d_in[16];
    const int*   g_dst        = (const int*)d_in[17];
    const int*   lg_src       = (const int*)d_in[18];
    const int*   lg_dst       = (const int*)d_in[19];
    const int*   pm_pd        = (const int*)d_in[20];

    float* out_x = (float*)d_out;
    float* out_y = (float*)d_out + (size_t)NN * F;

    float *zg0, *zg1, *zg2, *zgt, *pmy, *st;
    uint4 *zl0, *zl1, *zl2, *zlt;
    int *cnt, *incl, *off, *rank, *csr_src_g, *csr_eid_g, *csr_lg, *bsum;
    cudaGetSymbolAddress((void**)&zg0, d_zg0);
    cudaGetSymbolAddress((void**)&zg1, d_zg1);
    cudaGetSymbolAddress((void**)&zg2, d_zg2);
    cudaGetSymbolAddress((void**)&zgt, d_zgt);
    cudaGetSymbolAddress((void**)&pmy, d_pmy);
    cudaGetSymbolAddress((void**)&zl0, d_zl0);
    cudaGetSymbolAddress((void**)&zl1, d_zl1);
    cudaGetSymbolAddress((void**)&zl2, d_zl2);
    cudaGetSymbolAddress((void**)&zlt, d_zlt);
    cudaGetSymbolAddress((void**)&st,  d_stats);
    cudaGetSymbolAddress((void**)&cnt, d_cnt);
    cudaGetSymbolAddress((void**)&incl, d_incl);
    cudaGetSymbolAddress((void**)&off, d_off);
    cudaGetSymbolAddress((void**)&rank, d_rank);
    cudaGetSymbolAddress((void**)&csr_src_g, d_csr_src_g);
    cudaGetSymbolAddress((void**)&csr_eid_g, d_csr_eid_g);
    cudaGetSymbolAddress((void**)&csr_lg, d_csr_lg);
    cudaGetSymbolAddress((void**)&bsum, d_bsum);

    int* off_g  = off;
    int* off_lg = off + NN + 1;

    const int TB = 256;
    int e4Blocks = ((NE + NLE) / 4 + TB - 1) / TB;

    // ===== CSR build =====
    hist_both_kernel<<<e4Blocks, TB>>>(g_dst, lg_dst, cnt, rank, st);
    scan_block_kernel<<<SBG + SBL, SCAN_B>>>(cnt, incl, bsum);
    scan_add_kernel<<<SBG + SBL, SCAN_B>>>(incl, cnt, bsum, off);
    fill_both_kernel<<<e4Blocks, TB>>>(g_src, g_dst, lg_src, lg_dst,
                                       off_g, off_lg, rank,
                                       csr_src_g, csr_eid_g, csr_lg);

    // ===== hops: lg dual-row (NE*2 threads), g 8 thr/row =====
    long long rows1 = (long long)NE * 2 + (long long)NN * 8 + (long long)NN * 8;
    long long rows  = (long long)NE * 2 + (long long)NN * 8;
    int hBlocks1 = (int)((rows1 + TB - 1) / TB);
    int hBlocks  = (int)((rows + TB - 1) / TB);

    hops_kernel<<<hBlocks1, TB>>>(y, nullptr, off_lg, csr_lg, zl0,
                                  x, off_g, csr_src_g, zg0,
                                  y, csr_eid_g, pmy, NN, 0);
    hops_kernel<<<hBlocks, TB>>>(nullptr, zl0, off_lg, csr_lg, zl1,
                                 zg0, off_g, csr_src_g, zg1,
                                 nullptr, nullptr, nullptr, 0, 1);
    hops_kernel<<<hBlocks, TB>>>(nullptr, zl1, off_lg, csr_lg, zlt,
                                 zg1, off_g, csr_src_g, zgt,
                                 nullptr, nullptr, nullptr, 0, 1);
    hops_kernel<<<hBlocks, TB>>>(nullptr, zlt, off_lg, csr_lg, zl2,
                                 zgt, off_g, csr_src_g, zg2,
                                 nullptr, nullptr, nullptr, 0, 1);

    // ===== assemble =====
    int bx = (NN + TB - 1) / TB;
    int by = (NE + TB - 1) / TB;
    assemble_both_kernel<<<bx + by, TB>>>(
        x, deg_g, pmy, zg0, zg1, zg2,
        theta_main_w, theta_main_b, theta_list_w, theta_list_b, out_x, NN, bx,
        y, deg_lg, x, pm_pd, zl0, zl1, zl2,
        gamma_main_w, gamma_main_b, gamma_list_w, gamma_list_b, out_y, NE);

    // ===== batchnorm =====
    stats_both_kernel<<<512 + 2048, TB>>>(out_x, out_y, 512, st);
    normalize_both_kernel<<<512 + 2048, TB>>>(out_x, out_y, 512, st,
                                              bn_x_scale, bn_x_bias, bn_y_scale, bn_y_bias);
}

// round 16
// speedup vs baseline: 1.0939x; 1.0939x over previous
#include <cuda_runtime.h>
#include <cuda_fp16.h>
#include <cstddef>

#define NN   50000
#define NE   400000
#define NLE  3200000
#define F    32
#define SCAN_B 1024
#define SBG   ((NN + SCAN_B - 1) / SCAN_B)   // 49
#define SBL   ((NE + SCAN_B - 1) / SCAN_B)   // 391

typedef unsigned long long u64;

// ---------------- scratch (device globals) ----------------
__device__ float d_zg0[NN * F];
__device__ float d_zg1[NN * F];
__device__ float d_zg2[NN * F];
__device__ float d_zgt[NN * F];
__device__ float d_pmy[NN * F];
__device__ uint4 d_zl0[NE * F / 8];
__device__ uint4 d_zl1[NE * F / 8];
__device__ uint4 d_zl2[NE * F / 8];
__device__ uint4 d_zlt[NE * F / 8];
__device__ float d_stats[128];

__device__ int d_cnt[NN + NE];
__device__ int d_incl[NN + NE];
__device__ int d_off[(NN + 1) + (NE + 1)];
__device__ int d_rank[NE + NLE];
__device__ int d_csr_src_g[NE];
__device__ int d_csr_eid_g[NE];
__device__ int d_csr_lg[NLE];
__device__ int d_bsum[1024];

// ---------------- helpers ----------------
__device__ __forceinline__ u64 pack2(float a, float b) {
    u64 r; asm("mov.b64 %0, {%1, %2};" : "=l"(r) : "f"(a), "f"(b)); return r;
}
__device__ __forceinline__ void unpack2(u64 v, float& a, float& b) {
    asm("mov.b64 {%0, %1}, %2;" : "=f"(a), "=f"(b) : "l"(v));
}
__device__ __forceinline__ u64 fma2(u64 a, u64 b, u64 c) {
    u64 d; asm("fma.rn.f32x2 %0, %1, %2, %3;" : "=l"(d) : "l"(a), "l"(b), "l"(c)); return d;
}
__device__ __forceinline__ unsigned int pack_h2(float a, float b) {
    __half2 h = __floats2half2_rn(a, b);
    return *(unsigned int*)&h;
}
__device__ __forceinline__ void h2_acc(float& a, float& b, unsigned int u) {
    __half2 h = *(__half2*)&u;
    float2 f = __half22float2(h);
    a += f.x; b += f.y;
}

// ================= CSR build: 4 edges/thread, int4 IO =================
__global__ void hist_both_kernel(const int* __restrict__ g_dst, const int* __restrict__ lg_dst,
                                 int* __restrict__ cnt, int* __restrict__ rank,
                                 float* __restrict__ st) {
    if (blockIdx.x == 0 && threadIdx.x < 128) st[threadIdx.x] = 0.f;
    int t = blockIdx.x * blockDim.x + threadIdx.x;
    if (t < NE / 4) {
        int4 d = __ldg((const int4*)g_dst + t);
        int4 r;
        r.x = atomicAdd(&cnt[d.x], 1);
        r.y = atomicAdd(&cnt[d.y], 1);
        r.z = atomicAdd(&cnt[d.z], 1);
        r.w = atomicAdd(&cnt[d.w], 1);
        __stcs((int4*)rank + t, r);
    } else if (t < NE / 4 + NLE / 4) {
        int i = t - NE / 4;
        int4 d = __ldg((const int4*)lg_dst + i);
        int4 r;
        r.x = atomicAdd(&cnt[NN + d.x], 1);
        r.y = atomicAdd(&cnt[NN + d.y], 1);
        r.z = atomicAdd(&cnt[NN + d.z], 1);
        r.w = atomicAdd(&cnt[NN + d.w], 1);
        __stcs((int4*)(rank + NE) + i, r);
    }
}

__global__ void scan_block_kernel(const int* __restrict__ cnt, int* __restrict__ incl,
                                  int* __restrict__ bsum) {
    int b = blockIdx.x;
    const int* c; int* in; int n; int* bs; int rel;
    if (b < SBG) { c = cnt;      in = incl;      n = NN; bs = bsum;       rel = b; }
    else         { c = cnt + NN; in = incl + NN; n = NE; bs = bsum + 512; rel = b - SBG; }
    int tid = threadIdx.x;
    int lane = tid & 31, wid = tid >> 5;
    int i = rel * SCAN_B + tid;
    int v = (i < n) ? c[i] : 0;
    int sv = v;
#pragma unroll
    for (int o = 1; o < 32; o <<= 1) {
        int t2 = __shfl_up_sync(~0u, sv, o);
        if (lane >= o) sv += t2;
    }
    __shared__ int ws[32];
    if (lane == 31) ws[wid] = sv;
    __syncthreads();
    if (wid == 0) {
        int w = ws[lane];
#pragma unroll
        for (int o = 1; o < 32; o <<= 1) {
            int t2 = __shfl_up_sync(~0u, w, o);
            if (lane >= o) w += t2;
        }
        ws[lane] = w;
    }
    __syncthreads();
    int inc = sv + (wid ? ws[wid - 1] : 0);
    if (i < n) in[i] = inc;
    if (tid == SCAN_B - 1) bs[rel] = inc;
}

__global__ void scan_add_kernel(const int* __restrict__ incl, int* __restrict__ cnt,
                                const int* __restrict__ bsum, int* __restrict__ off) {
    int b = blockIdx.x;
    const int* in; int* c; int n; const int* bs; int rel; int* o_;
    if (b < SBG) { in = incl;      c = cnt;      n = NN; bs = bsum;       rel = b;       o_ = off; }
    else         { in = incl + NN; c = cnt + NN; n = NE; bs = bsum + 512; rel = b - SBG; o_ = off + NN + 1; }
    __shared__ int red[SCAN_B];
    int t = threadIdx.x;
    red[t] = (t < rel) ? bs[t] : 0;
    __syncthreads();
#pragma unroll
    for (int o = SCAN_B / 2; o > 0; o >>= 1) {
        if (t < o) red[t] += red[t + o];
        __syncthreads();
    }
    int prefix = red[0];
    int i = rel * SCAN_B + t;
    if (i < n) {
        o_[i + 1] = in[i] + prefix;
        c[i] = 0;
        if (i == 0) o_[0] = 0;
    }
}

__global__ void fill_both_kernel(const int* __restrict__ g_src, const int* __restrict__ g_dst,
                                 const int* __restrict__ lg_src, const int* __restrict__ lg_dst,
                                 const int* __restrict__ off_g, const int* __restrict__ off_lg,
                                 const int* __restrict__ rank,
                                 int* __restrict__ csr_src_g, int* __restrict__ csr_eid_g,
                                 int* __restrict__ csr_lg) {
    int t = blockIdx.x * blockDim.x + threadIdx.x;
    if (t < NE / 4) {
        int4 d  = __ldg((const int4*)g_dst + t);
        int4 rk = __ldcs((const int4*)rank + t);
        int4 s  = __ldg((const int4*)g_src + t);
        int e = 4 * t;
        int p0 = __ldg(off_g + d.x) + rk.x;
        int p1 = __ldg(off_g + d.y) + rk.y;
        int p2 = __ldg(off_g + d.z) + rk.z;
        int p3 = __ldg(off_g + d.w) + rk.w;
        __stcs(csr_src_g + p0, s.x); __stcs(csr_eid_g + p0, e);
        __stcs(csr_src_g + p1, s.y); __stcs(csr_eid_g + p1, e + 1);
        __stcs(csr_src_g + p2, s.z); __stcs(csr_eid_g + p2, e + 2);
        __stcs(csr_src_g + p3, s.w); __stcs(csr_eid_g + p3, e + 3);
    } else if (t < NE / 4 + NLE / 4) {
        int i = t - NE / 4;
        int4 d  = __ldg((const int4*)lg_dst + i);
        int4 rk = __ldcs((const int4*)(rank + NE) + i);
        int4 s  = __ldg((const int4*)lg_src + i);
        __stcs(csr_lg + __ldg(off_lg + d.x) + rk.x, s.x);
        __stcs(csr_lg + __ldg(off_lg + d.y) + rk.y, s.y);
        __stcs(csr_lg + __ldg(off_lg + d.z) + rk.z, s.z);
        __stcs(csr_lg + __ldg(off_lg + d.w) + rk.w, s.w);
    }
}

// ================= pull SpMM =================
__device__ __forceinline__ void pull_f32_f32(const float* __restrict__ z, const int* __restrict__ off,
                                             const int* __restrict__ idx, float* __restrict__ out,
                                             int r, int lane, unsigned m8) {
    int b = __ldg(off + r), e = __ldg(off + r + 1);
    float4 acc = make_float4(0.f, 0.f, 0.f, 0.f);
    int i = b;
    for (; i + 3 < e; i += 4) {
        int v = __ldg(idx + i + (lane & 3));
        int s0 = __shfl_sync(m8, v, 0, 8);
        int s1 = __shfl_sync(m8, v, 1, 8);
        int s2 = __shfl_sync(m8, v, 2, 8);
        int s3 = __shfl_sync(m8, v, 3, 8);
        float4 v0 = *((const float4*)(z + (size_t)s0 * F) + lane);
        float4 v1 = *((const float4*)(z + (size_t)s1 * F) + lane);
        float4 v2 = *((const float4*)(z + (size_t)s2 * F) + lane);
        float4 v3 = *((const float4*)(z + (size_t)s3 * F) + lane);
        acc.x += (v0.x + v1.x) + (v2.x + v3.x);
        acc.y += (v0.y + v1.y) + (v2.y + v3.y);
        acc.z += (v0.z + v1.z) + (v2.z + v3.z);
        acc.w += (v0.w + v1.w) + (v2.w + v3.w);
    }
    for (; i < e; i++) {
        int s0 = __ldg(idx + i);
        float4 v0 = *((const float4*)(z + (size_t)s0 * F) + lane);
        acc.x += v0.x; acc.y += v0.y; acc.z += v0.z; acc.w += v0.w;
    }
    __stcs((float4*)(out + (size_t)r * F) + lane, acc);
}

// fp32->fp16, 4 threads/row, idx dedup + next-quad prefetch pipeline
__device__ __forceinline__ void pull_f32_h4(const float* __restrict__ z, const int* __restrict__ off,
                                            const int* __restrict__ idx, uint4* __restrict__ out,
                                            int r, int lane, unsigned m4) {
    int b = __ldg(off + r), e = __ldg(off + r + 1);
    float a0 = 0.f, a1 = 0.f, a2 = 0.f, a3 = 0.f, a4 = 0.f, a5 = 0.f, a6 = 0.f, a7 = 0.f;
    int i = b;
    if (i + 3 < e) {
        int v = __ldg(idx + i + lane);
        for (; i + 7 < e; i += 4) {
            int vn = __ldg(idx + i + 4 + lane);   // prefetch next quad
            int s0 = __shfl_sync(m4, v, 0, 4);
            int s1 = __shfl_sync(m4, v, 1, 4);
            int s2 = __shfl_sync(m4, v, 2, 4);
            int s3 = __shfl_sync(m4, v, 3, 4);
#pragma unroll
            for (int q = 0; q < 4; q++) {
                int s = q == 0 ? s0 : (q == 1 ? s1 : (q == 2 ? s2 : s3));
                const float4* p = (const float4*)(z + (size_t)s * F) + lane * 2;
                float4 u0 = p[0], u1 = p[1];
                a0 += u0.x; a1 += u0.y; a2 += u0.z; a3 += u0.w;
                a4 += u1.x; a5 += u1.y; a6 += u1.z; a7 += u1.w;
            }
            v = vn;
        }
        {   // final full quad
            int s0 = __shfl_sync(m4, v, 0, 4);
            int s1 = __shfl_sync(m4, v, 1, 4);
            int s2 = __shfl_sync(m4, v, 2, 4);
            int s3 = __shfl_sync(m4, v, 3, 4);
#pragma unroll
            for (int q = 0; q < 4; q++) {
                int s = q == 0 ? s0 : (q == 1 ? s1 : (q == 2 ? s2 : s3));
                const float4* p = (const float4*)(z + (size_t)s * F) + lane * 2;
                float4 u0 = p[0], u1 = p[1];
                a0 += u0.x; a1 += u0.y; a2 += u0.z; a3 += u0.w;
                a4 += u1.x; a5 += u1.y; a6 += u1.z; a7 += u1.w;
            }
            i += 4;
        }
    }
    for (; i < e; i++) {
        int s0 = __ldg(idx + i);
        const float4* p = (const float4*)(z + (size_t)s0 * F) + lane * 2;
        float4 u0 = p[0], u1 = p[1];
        a0 += u0.x; a1 += u0.y; a2 += u0.z; a3 += u0.w;
        a4 += u1.x; a5 += u1.y; a6 += u1.z; a7 += u1.w;
    }
    uint4 o;
    o.x = pack_h2(a0, a1); o.y = pack_h2(a2, a3);
    o.z = pack_h2(a4, a5); o.w = pack_h2(a6, a7);
    __stcs(out + (size_t)r * 4 + lane, o);
}

// fp16->fp16, 4 threads/row, idx dedup + next-quad prefetch pipeline
__device__ __forceinline__ void pull_h_h4(const uint4* __restrict__ z, const int* __restrict__ off,
                                          const int* __restrict__ idx, uint4* __restrict__ out,
                                          int r, int lane, unsigned m4) {
    int b = __ldg(off + r), e = __ldg(off + r + 1);
    float a0 = 0.f, a1 = 0.f, a2 = 0.f, a3 = 0.f, a4 = 0.f, a5 = 0.f, a6 = 0.f, a7 = 0.f;
    int i = b;
    if (i + 3 < e) {
        int v = __ldg(idx + i + lane);
        for (; i + 7 < e; i += 4) {
            int vn = __ldg(idx + i + 4 + lane);
            int s0 = __shfl_sync(m4, v, 0, 4);
            int s1 = __shfl_sync(m4, v, 1, 4);
            int s2 = __shfl_sync(m4, v, 2, 4);
            int s3 = __shfl_sync(m4, v, 3, 4);
            uint4 v0 = __ldg(z + (size_t)s0 * 4 + lane);
            uint4 v1 = __ldg(z + (size_t)s1 * 4 + lane);
            uint4 v2 = __ldg(z + (size_t)s2 * 4 + lane);
            uint4 v3 = __ldg(z + (size_t)s3 * 4 + lane);
            h2_acc(a0, a1, v0.x); h2_acc(a2, a3, v0.y); h2_acc(a4, a5, v0.z); h2_acc(a6, a7, v0.w);
            h2_acc(a0, a1, v1.x); h2_acc(a2, a3, v1.y); h2_acc(a4, a5, v1.z); h2_acc(a6, a7, v1.w);
            h2_acc(a0, a1, v2.x); h2_acc(a2, a3, v2.y); h2_acc(a4, a5, v2.z); h2_acc(a6, a7, v2.w);
            h2_acc(a0, a1, v3.x); h2_acc(a2, a3, v3.y); h2_acc(a4, a5, v3.z); h2_acc(a6, a7, v3.w);
            v = vn;
        }
        {
            int s0 = __shfl_sync(m4, v, 0, 4);
            int s1 = __shfl_sync(m4, v, 1, 4);
            int s2 = __shfl_sync(m4, v, 2, 4);
            int s3 = __shfl_sync(m4, v, 3, 4);
            uint4 v0 = __ldg(z + (size_t)s0 * 4 + lane);
            uint4 v1 = __ldg(z + (size_t)s1 * 4 + lane);
            uint4 v2 = __ldg(z + (size_t)s2 * 4 + lane);
            uint4 v3 = __ldg(z + (size_t)s3 * 4 + lane);
            h2_acc(a0, a1, v0.x); h2_acc(a2, a3, v0.y); h2_acc(a4, a5, v0.z); h2_acc(a6, a7, v0.w);
            h2_acc(a0, a1, v1.x); h2_acc(a2, a3, v1.y); h2_acc(a4, a5, v1.z); h2_acc(a6, a7, v1.w);
            h2_acc(a0, a1, v2.x); h2_acc(a2, a3, v2.y); h2_acc(a4, a5, v2.z); h2_acc(a6, a7, v2.w);
            h2_acc(a0, a1, v3.x); h2_acc(a2, a3, v3.y); h2_acc(a4, a5, v3.z); h2_acc(a6, a7, v3.w);
            i += 4;
        }
    }
    for (; i < e; i++) {
        int s0 = __ldg(idx + i);
        uint4 v0 = __ldg(z + (size_t)s0 * 4 + lane);
        h2_acc(a0, a1, v0.x); h2_acc(a2, a3, v0.y); h2_acc(a4, a5, v0.z); h2_acc(a6, a7, v0.w);
    }
    uint4 o;
    o.x = pack_h2(a0, a1); o.y = pack_h2(a2, a3);
    o.z = pack_h2(a4, a5); o.w = pack_h2(a6, a7);
    __stcs(out + (size_t)r * 4 + lane, o);
}

// mode 0: hop1 (lg fp32->h4, g fp32, pmy) ; mode 1: hops 2-4 (lg h4->h4, g fp32)
__global__ void hops_kernel(
    const float* __restrict__ zf, const uint4* __restrict__ zh,
    const int* __restrict__ off_lg, const int* __restrict__ csr_lg, uint4* __restrict__ o_lg,
    const float* __restrict__ zg, const int* __restrict__ off_g, const int* __restrict__ csr_g,
    float* __restrict__ o_g,
    const float* __restrict__ y3, const int* __restrict__ eid3, float* __restrict__ o3, int n3,
    int mode)
{
    long long t = (long long)blockIdx.x * blockDim.x + threadIdx.x;
    int wlane = threadIdx.x & 31;
    const long long lgT = (long long)NE * 4;
    if (t < lgT) {
        int r = (int)(t >> 2), lane = (int)(t & 3);
        unsigned m4 = 0xFu << (wlane & 28);
        if (mode == 0) pull_f32_h4(zf, off_lg, csr_lg, o_lg, r, lane, m4);
        else           pull_h_h4(zh, off_lg, csr_lg, o_lg, r, lane, m4);
    } else {
        long long t2 = t - lgT;
        unsigned m8 = 0xFFu << (wlane & 24);
        if (t2 < (long long)NN * 8) {
            pull_f32_f32(zg, off_g, csr_g, o_g, (int)(t2 >> 3), (int)(t2 & 7), m8);
        } else {
            long long t3 = t2 - (long long)NN * 8;
            if (t3 < (long long)n3 * 8)
                pull_f32_f32(y3, off_g, eid3, o3, (int)(t3 >> 3), (int)(t3 & 7), m8);
        }
    }
}

// ================= fused assemble (f32x2) =================
__device__ __forceinline__ void mv_acc2(u64 acc[16], const float* __restrict__ vec,
                                        float scale, const u64 (&W)[F][16], bool streaming) {
#pragma unroll 1
    for (int k4 = 0; k4 < 8; k4++) {
        float4 v = streaming ? __ldcs((const float4*)vec + k4) : *((const float4*)vec + k4);
        float c0 = v.x * scale, c1 = v.y * scale, c2 = v.z * scale, c3 = v.w * scale;
        u64 a0 = pack2(c0, c0), a1 = pack2(c1, c1), a2 = pack2(c2, c2), a3 = pack2(c3, c3);
#pragma unroll
        for (int j = 0; j < 16; j++) acc[j] = fma2(a0, W[k4 * 4 + 0][j], acc[j]);
#pragma unroll
        for (int j = 0; j < 16; j++) acc[j] = fma2(a1, W[k4 * 4 + 1][j], acc[j]);
#pragma unroll
        for (int j = 0; j < 16; j++) acc[j] = fma2(a2, W[k4 * 4 + 2][j], acc[j]);
#pragma unroll
        for (int j = 0; j < 16; j++) acc[j] = fma2(a3, W[k4 * 4 + 3][j], acc[j]);
    }
}

__device__ __forceinline__ void mv_acc2_h(u64 acc[16], const uint4* __restrict__ vec,
                                          const u64 (&W)[F][16]) {
#pragma unroll 1
    for (int q = 0; q < 4; q++) {
        uint4 u = __ldcs(vec + q);
        float f0, f1, f2, f3, f4, f5, f6, f7;
        { __half2 h = *(__half2*)&u.x; float2 f = __half22float2(h); f0 = f.x; f1 = f.y; }
        { __half2 h = *(__half2*)&u.y; float2 f = __half22float2(h); f2 = f.x; f3 = f.y; }
        { __half2 h = *(__half2*)&u.z; float2 f = __half22float2(h); f4 = f.x; f5 = f.y; }
        { __half2 h = *(__half2*)&u.w; float2 f = __half22float2(h); f6 = f.x; f7 = f.y; }
        u64 a0 = pack2(f0, f0), a1 = pack2(f1, f1), a2 = pack2(f2, f2), a3 = pack2(f3, f3);
        u64 a4 = pack2(f4, f4), a5 = pack2(f5, f5), a6 = pack2(f6, f6), a7 = pack2(f7, f7);
        int k = q * 8;
#pragma unroll
        for (int j = 0; j < 16; j++) acc[j] = fma2(a0, W[k + 0][j], acc[j]);
#pragma unroll
        for (int j = 0; j < 16; j++) acc[j] = fma2(a1, W[k + 1][j], acc[j]);
#pragma unroll
        for (int j = 0; j < 16; j++) acc[j] = fma2(a2, W[k + 2][j], acc[j]);
#pragma unroll
        for (int j = 0; j < 16; j++) acc[j] = fma2(a3, W[k + 3][j], acc[j]);
#pragma unroll
        for (int j = 0; j < 16; j++) acc[j] = fma2(a4, W[k + 4][j], acc[j]);
#pragma unroll
        for (int j = 0; j < 16; j++) acc[j] = fma2(a5, W[k + 5][j], acc[j]);
#pragma unroll
        for (int j = 0; j < 16; j++) acc[j] = fma2(a6, W[k + 6][j], acc[j]);
#pragma unroll
        for (int j = 0; j < 16; j++) acc[j] = fma2(a7, W[k + 7][j], acc[j]);
    }
}

__global__ void assemble_both_kernel(
    const float* __restrict__ xb, const float* __restrict__ xdeg, const float* __restrict__ xextra,
    const float* __restrict__ xz0, const float* __restrict__ xz1, const float* __restrict__ xz2,
    const float* __restrict__ xWm, const float* __restrict__ xbm,
    const float* __restrict__ xWl, const float* __restrict__ xbl,
    float* __restrict__ xout, int nx, int bx,
    const float* __restrict__ yb, const float* __restrict__ ydeg, const float* __restrict__ yextra,
    const int* __restrict__ gatherIdx,
    const uint4* __restrict__ yz0, const uint4* __restrict__ yz1, const uint4* __restrict__ yz2,
    const float* __restrict__ yWm, const float* __restrict__ ybm,
    const float* __restrict__ yWl, const float* __restrict__ ybl,
    float* __restrict__ yout, int ny)
{
    bool isX = (int)blockIdx.x < bx;
    const float* Wmain = isX ? xWm : yWm;
    const float* bmain = isX ? xbm : ybm;
    const float* Wlist = isX ? xWl : yWl;
    const float* blist = isX ? xbl : ybl;

    __shared__ u64 sW[6][F][16];
    __shared__ u64 sb[16];
    for (int i = threadIdx.x; i < 6 * F * 16; i += blockDim.x) {
        int m = i >> 9;
        int rem = i & 511;
        int k = rem >> 4;
        int j2 = rem & 15;
        const float* W = (m < 3) ? (Wmain + m * 1024) : (Wlist + (m - 3) * 1024);
        sW[m][k][j2] = pack2(W[(2 * j2) * 32 + k], W[(2 * j2 + 1) * 32 + k]);
    }
    if (threadIdx.x < 16) {
        int j2 = threadIdx.x;
        float b0 = 0.f, b1 = 0.f;
#pragma unroll
        for (int m = 0; m < 3; m++) {
            b0 += bmain[m * 32 + 2 * j2] + blist[m * 32 + 2 * j2];
            b1 += bmain[m * 32 + 2 * j2 + 1] + blist[m * 32 + 2 * j2 + 1];
        }
        sb[j2] = pack2(b0, b1);
    }
    __syncthreads();

    u64 acc[16];
#pragma unroll
    for (int j = 0; j < 16; j++) acc[j] = sb[j];

    float* out;
    int r;
    if (isX) {
        r = (int)blockIdx.x * blockDim.x + threadIdx.x;
        if (r >= nx) return;
        out = xout;
        size_t r32 = (size_t)r * F;
        float dg = xdeg[r];
        mv_acc2(acc, xb + r32, 1.f, sW[0], false);
        mv_acc2(acc, xb + r32, dg,  sW[1], false);
        mv_acc2(acc, xextra + r32, 1.f, sW[2], true);
        mv_acc2(acc, xz0 + r32, 1.f, sW[3], true);
        mv_acc2(acc, xz1 + r32, 1.f, sW[4], true);
        mv_acc2(acc, xz2 + r32, 1.f, sW[5], true);
    } else {
        r = ((int)blockIdx.x - bx) * blockDim.x + threadIdx.x;
        if (r >= ny) return;
        out = yout;
        size_t r32 = (size_t)r * F;
        float dg = ydeg[r];
        mv_acc2(acc, yb + r32, 1.f, sW[0], false);
        mv_acc2(acc, yb + r32, dg,  sW[1], false);
        mv_acc2(acc, yextra + (size_t)__ldg(gatherIdx + r) * F, 1.f, sW[2], false);
        mv_acc2_h(acc, yz0 + (size_t)r * 4, sW[3]);
        mv_acc2_h(acc, yz1 + (size_t)r * 4, sW[4]);
        mv_acc2_h(acc, yz2 + (size_t)r * 4, sW[5]);
    }

    float vals[F];
#pragma unroll
    for (int j = 0; j < 16; j++) unpack2(acc[j], vals[2 * j], vals[2 * j + 1]);
#pragma unroll
    for (int j = F / 2; j < F; j++) vals[j] = fmaxf(vals[j], 0.f);

    float4* op = (float4*)(out + (size_t)r * F);
#pragma unroll
    for (int j = 0; j < 8; j++)
        op[j] = make_float4(vals[4 * j], vals[4 * j + 1], vals[4 * j + 2], vals[4 * j + 3]);
}

// ================= BN stats =================
__global__ void stats_both_kernel(const float* __restrict__ vx, const float* __restrict__ vy,
                                  int gx, float* __restrict__ st) {
    bool isX = (int)blockIdx.x < gx;
    const float* v = isX ? vx : vy;
    long long nRows = isX ? NN : NE;
    float* s0 = st + (isX ? 0 : 64);
    int nb = isX ? gx : (gridDim.x - gx);
    int rb = isX ? (int)blockIdx.x : (int)blockIdx.x - gx;

    int col = threadIdx.x & 31;
    int w = threadIdx.x >> 5;
    int warpsPerBlock = blockDim.x >> 5;
    float s = 0.f, s2 = 0.f;
    for (long long r = (long long)rb * warpsPerBlock + w; r < nRows;
         r += (long long)nb * warpsPerBlock) {
        float val = v[r * F + col];
        s += val;
        s2 += val * val;
    }
    __shared__ float sm[2][8][F];
    sm[0][w][col] = s;
    sm[1][w][col] = s2;
    __syncthreads();
    if (threadIdx.x < F) {
        float a = 0.f, b = 0.f;
#pragma unroll
        for (int ww = 0; ww < 8; ww++) { a += sm[0][ww][threadIdx.x]; b += sm[1][ww][threadIdx.x]; }
        atomicAdd(&s0[threadIdx.x], a);
        atomicAdd(&s0[F + threadIdx.x], b);
    }
}

// ================= BN normalize =================
__global__ void normalize_both_kernel(float* __restrict__ vx, float* __restrict__ vy,
                                      int gx, const float* __restrict__ st,
                                      const float* __restrict__ sx, const float* __restrict__ bxx,
                                      const float* __restrict__ sy, const float* __restrict__ byy) {
    bool isX = (int)blockIdx.x < gx;
    float* v = isX ? vx : vy;
    long long nRows = isX ? NN : NE;
    const float* s0 = st + (isX ? 0 : 64);
    const float* scale = isX ? sx : sy;
    const float* bias  = isX ? bxx : byy;
    int nb = isX ? gx : (gridDim.x - gx);
    int rb = isX ? (int)blockIdx.x : (int)blockIdx.x - gx;

    __shared__ float mulc[F], addc[F];
    if (threadIdx.x < F) {
        float m = s0[threadIdx.x] / (float)nRows;
        float var = s0[F + threadIdx.x] / (float)nRows - m * m;
        float g = rsqrtf(var + 1e-5f) * scale[threadIdx.x];
        mulc[threadIdx.x] = g;
        addc[threadIdx.x] = bias[threadIdx.x] - m * g;
    }
    __syncthreads();
    int col = threadIdx.x & 31;
    int w = threadIdx.x >> 5;
    int warpsPerBlock = blockDim.x >> 5;
    for (long long r = (long long)rb * warpsPerBlock + w; r < nRows;
         r += (long long)nb * warpsPerBlock) {
        v[r * F + col] = fmaf(v[r * F + col], mulc[col], addc[col]);
    }
}

// ================= launcher =================
extern "C" void kernel_launch(void* const* d_in, const int* in_sizes, int n_in,
                              void* d_out, int out_size) {
    const float* x            = (const float*)d_in[0];
    const float* y            = (const float*)d_in[1];
    const float* deg_g        = (const float*)d_in[2];
    const float* deg_lg       = (const float*)d_in[3];
    const float* theta_main_w = (const float*)d_in[4];
    const float* theta_main_b = (const float*)d_in[5];
    const float* theta_list_w = (const float*)d_in[6];
    const float* theta_list_b = (const float*)d_in[7];
    const float* gamma_main_w = (const float*)d_in[8];
    const float* gamma_main_b = (const float*)d_in[9];
    const float* gamma_list_w = (const float*)d_in[10];
    const float* gamma_list_b = (const float*)d_in[11];
    const float* bn_x_scale   = (const float*)d_in[12];
    const float* bn_x_bias    = (const float*)d_in[13];
    const float* bn_y_scale   = (const float*)d_in[14];
    const float* bn_y_bias    = (const float*)d_in[15];
    const int*   g_src        = (const int*)d_in[16];
    const int*   g_dst        = (const int*)d_in[17];
    const int*   lg_src       = (const int*)d_in[18];
    const int*   lg_dst       = (const int*)d_in[19];
    const int*   pm_pd        = (const int*)d_in[20];

    float* out_x = (float*)d_out;
    float* out_y = (float*)d_out + (size_t)NN * F;

    float *zg0, *zg1, *zg2, *zgt, *pmy, *st;
    uint4 *zl0, *zl1, *zl2, *zlt;
    int *cnt, *incl, *off, *rank, *csr_src_g, *csr_eid_g, *csr_lg, *bsum;
    cudaGetSymbolAddress((void**)&zg0, d_zg0);
    cudaGetSymbolAddress((void**)&zg1, d_zg1);
    cudaGetSymbolAddress((void**)&zg2, d_zg2);
    cudaGetSymbolAddress((void**)&zgt, d_zgt);
    cudaGetSymbolAddress((void**)&pmy, d_pmy);
    cudaGetSymbolAddress((void**)&zl0, d_zl0);
    cudaGetSymbolAddress((void**)&zl1, d_zl1);
    cudaGetSymbolAddress((void**)&zl2, d_zl2);
    cudaGetSymbolAddress((void**)&zlt, d_zlt);
    cudaGetSymbolAddress((void**)&st,  d_stats);
    cudaGetSymbolAddress((void**)&cnt, d_cnt);
    cudaGetSymbolAddress((void**)&incl, d_incl);
    cudaGetSymbolAddress((void**)&off, d_off);
    cudaGetSymbolAddress((void**)&rank, d_rank);
    cudaGetSymbolAddress((void**)&csr_src_g, d_csr_src_g);
    cudaGetSymbolAddress((void**)&csr_eid_g, d_csr_eid_g);
    cudaGetSymbolAddress((void**)&csr_lg, d_csr_lg);
    cudaGetSymbolAddress((void**)&bsum, d_bsum);

    int* off_g  = off;
    int* off_lg = off + NN + 1;

    const int TB = 256;
    int e4Blocks = ((NE + NLE) / 4 + TB - 1) / TB;

    // ===== CSR build =====
    hist_both_kernel<<<e4Blocks, TB>>>(g_dst, lg_dst, cnt, rank, st);
    scan_block_kernel<<<SBG + SBL, SCAN_B>>>(cnt, incl, bsum);
    scan_add_kernel<<<SBG + SBL, SCAN_B>>>(incl, cnt, bsum, off);
    fill_both_kernel<<<e4Blocks, TB>>>(g_src, g_dst, lg_src, lg_dst,
                                       off_g, off_lg, rank,
                                       csr_src_g, csr_eid_g, csr_lg);

    // ===== hops: lg 4 thr/row, g 8 thr/row =====
    long long rows1 = (long long)NE * 4 + (long long)NN * 8 + (long long)NN * 8;
    long long rows  = (long long)NE * 4 + (long long)NN * 8;
    int hBlocks1 = (int)((rows1 + TB - 1) / TB);
    int hBlocks  = (int)((rows + TB - 1) / TB);

    hops_kernel<<<hBlocks1, TB>>>(y, nullptr, off_lg, csr_lg, zl0,
                                  x, off_g, csr_src_g, zg0,
                                  y, csr_eid_g, pmy, NN, 0);
    hops_kernel<<<hBlocks, TB>>>(nullptr, zl0, off_lg, csr_lg, zl1,
                                 zg0, off_g, csr_src_g, zg1,
                                 nullptr, nullptr, nullptr, 0, 1);
    hops_kernel<<<hBlocks, TB>>>(nullptr, zl1, off_lg, csr_lg, zlt,
                                 zg1, off_g, csr_src_g, zgt,
                                 nullptr, nullptr, nullptr, 0, 1);
    hops_kernel<<<hBlocks, TB>>>(nullptr, zlt, off_lg, csr_lg, zl2,
                                 zgt, off_g, csr_src_g, zg2,
                                 nullptr, nullptr, nullptr, 0, 1);

    // ===== assemble =====
    int bx = (NN + TB - 1) / TB;
    int by = (NE + TB - 1) / TB;
    assemble_both_kernel<<<bx + by, TB>>>(
        x, deg_g, pmy, zg0, zg1, zg2,
        theta_main_w, theta_main_b, theta_list_w, theta_list_b, out_x, NN, bx,
        y, deg_lg, x, pm_pd, zl0, zl1, zl2,
        gamma_main_w, gamma_main_b, gamma_list_w, gamma_list_b, out_y, NE);

    // ===== batchnorm =====
    stats_both_kernel<<<512 + 2048, TB>>>(out_x, out_y, 512, st);
    normalize_both_kernel<<<512 + 2048, TB>>>(out_x, out_y, 512, st,
                                              bn_x_scale, bn_x_bias, bn_y_scale, bn_y_bias);
}

// round 17
// speedup vs baseline: 1.1259x; 1.0293x over previous
#include <cuda_runtime.h>
#include <cuda_fp16.h>
#include <cstddef>

#define NN   50000
#define NE   400000
#define NLE  3200000
#define F    32
#define SCAN_B 1024
#define SBG   ((NN + SCAN_B - 1) / SCAN_B)   // 49
#define SBL   ((NE + SCAN_B - 1) / SCAN_B)   // 391

typedef unsigned long long u64;

// ---------------- scratch (device globals) ----------------
__device__ float d_zg0[NN * F];
__device__ float d_zg1[NN * F];
__device__ float d_zg2[NN * F];
__device__ float d_zgt[NN * F];
__device__ float d_pmy[NN * F];
__device__ uint4 d_zl0[NE * F / 8];
__device__ uint4 d_zl1[NE * F / 8];
__device__ uint4 d_zl2[NE * F / 8];
__device__ uint4 d_zlt[NE * F / 8];
__device__ float d_stats[128];

__device__ int d_cnt[NN + NE];
__device__ int d_incl[NN + NE];
__device__ int d_off[(NN + 1) + (NE + 1)];
__device__ int d_rank[NE + NLE];
__device__ int d_csr_src_g[NE];
__device__ int d_csr_eid_g[NE];
__device__ int d_csr_lg[NLE];
__device__ int d_bsum[1024];

// ---------------- helpers ----------------
__device__ __forceinline__ u64 pack2(float a, float b) {
    u64 r; asm("mov.b64 %0, {%1, %2};" : "=l"(r) : "f"(a), "f"(b)); return r;
}
__device__ __forceinline__ void unpack2(u64 v, float& a, float& b) {
    asm("mov.b64 {%0, %1}, %2;" : "=f"(a), "=f"(b) : "l"(v));
}
__device__ __forceinline__ u64 fma2(u64 a, u64 b, u64 c) {
    u64 d; asm("fma.rn.f32x2 %0, %1, %2, %3;" : "=l"(d) : "l"(a), "l"(b), "l"(c)); return d;
}
__device__ __forceinline__ unsigned int pack_h2(float a, float b) {
    __half2 h = __floats2half2_rn(a, b);
    return *(unsigned int*)&h;
}
__device__ __forceinline__ void h2_acc(float& a, float& b, unsigned int u) {
    __half2 h = *(__half2*)&u;
    float2 f = __half22float2(h);
    a += f.x; b += f.y;
}

// ================= CSR build: 4 edges/thread, int4 IO =================
__global__ void hist_both_kernel(const int* __restrict__ g_dst, const int* __restrict__ lg_dst,
                                 int* __restrict__ cnt, int* __restrict__ rank,
                                 float* __restrict__ st) {
    if (blockIdx.x == 0 && threadIdx.x < 128) st[threadIdx.x] = 0.f;
    int t = blockIdx.x * blockDim.x + threadIdx.x;
    if (t < NE / 4) {
        int4 d = __ldg((const int4*)g_dst + t);
        int4 r;
        r.x = atomicAdd(&cnt[d.x], 1);
        r.y = atomicAdd(&cnt[d.y], 1);
        r.z = atomicAdd(&cnt[d.z], 1);
        r.w = atomicAdd(&cnt[d.w], 1);
        __stcs((int4*)rank + t, r);
    } else if (t < NE / 4 + NLE / 4) {
        int i = t - NE / 4;
        int4 d = __ldg((const int4*)lg_dst + i);
        int4 r;
        r.x = atomicAdd(&cnt[NN + d.x], 1);
        r.y = atomicAdd(&cnt[NN + d.y], 1);
        r.z = atomicAdd(&cnt[NN + d.z], 1);
        r.w = atomicAdd(&cnt[NN + d.w], 1);
        __stcs((int4*)(rank + NE) + i, r);
    }
}

__global__ void scan_block_kernel(const int* __restrict__ cnt, int* __restrict__ incl,
                                  int* __restrict__ bsum) {
    int b = blockIdx.x;
    const int* c; int* in; int n; int* bs; int rel;
    if (b < SBG) { c = cnt;      in = incl;      n = NN; bs = bsum;       rel = b; }
    else         { c = cnt + NN; in = incl + NN; n = NE; bs = bsum + 512; rel = b - SBG; }
    int tid = threadIdx.x;
    int lane = tid & 31, wid = tid >> 5;
    int i = rel * SCAN_B + tid;
    int v = (i < n) ? c[i] : 0;
    int sv = v;
#pragma unroll
    for (int o = 1; o < 32; o <<= 1) {
        int t2 = __shfl_up_sync(~0u, sv, o);
        if (lane >= o) sv += t2;
    }
    __shared__ int ws[32];
    if (lane == 31) ws[wid] = sv;
    __syncthreads();
    if (wid == 0) {
        int w = ws[lane];
#pragma unroll
        for (int o = 1; o < 32; o <<= 1) {
            int t2 = __shfl_up_sync(~0u, w, o);
            if (lane >= o) w += t2;
        }
        ws[lane] = w;
    }
    __syncthreads();
    int inc = sv + (wid ? ws[wid - 1] : 0);
    if (i < n) in[i] = inc;
    if (tid == SCAN_B - 1) bs[rel] = inc;
}

__global__ void scan_add_kernel(const int* __restrict__ incl, int* __restrict__ cnt,
                                const int* __restrict__ bsum, int* __restrict__ off) {
    int b = blockIdx.x;
    const int* in; int* c; int n; const int* bs; int rel; int* o_;
    if (b < SBG) { in = incl;      c = cnt;      n = NN; bs = bsum;       rel = b;       o_ = off; }
    else         { in = incl + NN; c = cnt + NN; n = NE; bs = bsum + 512; rel = b - SBG; o_ = off + NN + 1; }
    __shared__ int red[SCAN_B];
    int t = threadIdx.x;
    red[t] = (t < rel) ? bs[t] : 0;
    __syncthreads();
#pragma unroll
    for (int o = SCAN_B / 2; o > 0; o >>= 1) {
        if (t < o) red[t] += red[t + o];
        __syncthreads();
    }
    int prefix = red[0];
    int i = rel * SCAN_B + t;
    if (i < n) {
        o_[i + 1] = in[i] + prefix;
        c[i] = 0;
        if (i == 0) o_[0] = 0;
    }
}

__global__ void fill_both_kernel(const int* __restrict__ g_src, const int* __restrict__ g_dst,
                                 const int* __restrict__ lg_src, const int* __restrict__ lg_dst,
                                 const int* __restrict__ off_g, const int* __restrict__ off_lg,
                                 const int* __restrict__ rank,
                                 int* __restrict__ csr_src_g, int* __restrict__ csr_eid_g,
                                 int* __restrict__ csr_lg) {
    int t = blockIdx.x * blockDim.x + threadIdx.x;
    if (t < NE / 4) {
        int4 d  = __ldg((const int4*)g_dst + t);
        int4 rk = __ldcs((const int4*)rank + t);
        int4 s  = __ldg((const int4*)g_src + t);
        int e = 4 * t;
        int p0 = __ldg(off_g + d.x) + rk.x;
        int p1 = __ldg(off_g + d.y) + rk.y;
        int p2 = __ldg(off_g + d.z) + rk.z;
        int p3 = __ldg(off_g + d.w) + rk.w;
        __stcs(csr_src_g + p0, s.x); __stcs(csr_eid_g + p0, e);
        __stcs(csr_src_g + p1, s.y); __stcs(csr_eid_g + p1, e + 1);
        __stcs(csr_src_g + p2, s.z); __stcs(csr_eid_g + p2, e + 2);
        __stcs(csr_src_g + p3, s.w); __stcs(csr_eid_g + p3, e + 3);
    } else if (t < NE / 4 + NLE / 4) {
        int i = t - NE / 4;
        int4 d  = __ldg((const int4*)lg_dst + i);
        int4 rk = __ldcs((const int4*)(rank + NE) + i);
        int4 s  = __ldg((const int4*)lg_src + i);
        __stcs(csr_lg + __ldg(off_lg + d.x) + rk.x, s.x);
        __stcs(csr_lg + __ldg(off_lg + d.y) + rk.y, s.y);
        __stcs(csr_lg + __ldg(off_lg + d.z) + rk.z, s.z);
        __stcs(csr_lg + __ldg(off_lg + d.w) + rk.w, s.w);
    }
}

// ================= pull SpMM =================
__device__ __forceinline__ void pull_f32_f32(const float* __restrict__ z, const int* __restrict__ off,
                                             const int* __restrict__ idx, float* __restrict__ out,
                                             int r, int lane, unsigned m8) {
    int b = __ldg(off + r), e = __ldg(off + r + 1);
    float4 acc = make_float4(0.f, 0.f, 0.f, 0.f);
    int i = b;
    for (; i + 3 < e; i += 4) {
        int v = __ldg(idx + i + (lane & 3));
        int s0 = __shfl_sync(m8, v, 0, 8);
        int s1 = __shfl_sync(m8, v, 1, 8);
        int s2 = __shfl_sync(m8, v, 2, 8);
        int s3 = __shfl_sync(m8, v, 3, 8);
        float4 v0 = *((const float4*)(z + (size_t)s0 * F) + lane);
        float4 v1 = *((const float4*)(z + (size_t)s1 * F) + lane);
        float4 v2 = *((const float4*)(z + (size_t)s2 * F) + lane);
        float4 v3 = *((const float4*)(z + (size_t)s3 * F) + lane);
        acc.x += (v0.x + v1.x) + (v2.x + v3.x);
        acc.y += (v0.y + v1.y) + (v2.y + v3.y);
        acc.z += (v0.z + v1.z) + (v2.z + v3.z);
        acc.w += (v0.w + v1.w) + (v2.w + v3.w);
    }
    for (; i < e; i++) {
        int s0 = __ldg(idx + i);
        float4 v0 = *((const float4*)(z + (size_t)s0 * F) + lane);
        acc.x += v0.x; acc.y += v0.y; acc.z += v0.z; acc.w += v0.w;
    }
    __stcs((float4*)(out + (size_t)r * F) + lane, acc);
}

// fp32->fp16, 4 threads/row, idx 4x-dedup via width-4 shfl
__device__ __forceinline__ void pull_f32_h4(const float* __restrict__ z, const int* __restrict__ off,
                                            const int* __restrict__ idx, uint4* __restrict__ out,
                                            int r, int lane, unsigned m4) {
    int b = __ldg(off + r), e = __ldg(off + r + 1);
    float a0 = 0.f, a1 = 0.f, a2 = 0.f, a3 = 0.f, a4 = 0.f, a5 = 0.f, a6 = 0.f, a7 = 0.f;
    int i = b;
    for (; i + 3 < e; i += 4) {
        int v = __ldg(idx + i + lane);
        int s0 = __shfl_sync(m4, v, 0, 4);
        int s1 = __shfl_sync(m4, v, 1, 4);
        int s2 = __shfl_sync(m4, v, 2, 4);
        int s3 = __shfl_sync(m4, v, 3, 4);
#pragma unroll
        for (int q = 0; q < 4; q++) {
            int s = q == 0 ? s0 : (q == 1 ? s1 : (q == 2 ? s2 : s3));
            const float4* p = (const float4*)(z + (size_t)s * F) + lane * 2;
            float4 u0 = p[0], u1 = p[1];
            a0 += u0.x; a1 += u0.y; a2 += u0.z; a3 += u0.w;
            a4 += u1.x; a5 += u1.y; a6 += u1.z; a7 += u1.w;
        }
    }
    for (; i < e; i++) {
        int s0 = __ldg(idx + i);
        const float4* p = (const float4*)(z + (size_t)s0 * F) + lane * 2;
        float4 u0 = p[0], u1 = p[1];
        a0 += u0.x; a1 += u0.y; a2 += u0.z; a3 += u0.w;
        a4 += u1.x; a5 += u1.y; a6 += u1.z; a7 += u1.w;
    }
    uint4 o;
    o.x = pack_h2(a0, a1); o.y = pack_h2(a2, a3);
    o.z = pack_h2(a4, a5); o.w = pack_h2(a6, a7);
    __stcs(out + (size_t)r * 4 + lane, o);
}

// fp16->fp16, 4 threads/row, idx 4x-dedup via width-4 shfl
__device__ __forceinline__ void pull_h_h4(const uint4* __restrict__ z, const int* __restrict__ off,
                                          const int* __restrict__ idx, uint4* __restrict__ out,
                                          int r, int lane, unsigned m4) {
    int b = __ldg(off + r), e = __ldg(off + r + 1);
    float a0 = 0.f, a1 = 0.f, a2 = 0.f, a3 = 0.f, a4 = 0.f, a5 = 0.f, a6 = 0.f, a7 = 0.f;
    int i = b;
    for (; i + 3 < e; i += 4) {
        int v = __ldg(idx + i + lane);
        int s0 = __shfl_sync(m4, v, 0, 4);
        int s1 = __shfl_sync(m4, v, 1, 4);
        int s2 = __shfl_sync(m4, v, 2, 4);
        int s3 = __shfl_sync(m4, v, 3, 4);
        uint4 v0 = __ldg(z + (size_t)s0 * 4 + lane);
        uint4 v1 = __ldg(z + (size_t)s1 * 4 + lane);
        uint4 v2 = __ldg(z + (size_t)s2 * 4 + lane);
        uint4 v3 = __ldg(z + (size_t)s3 * 4 + lane);
        h2_acc(a0, a1, v0.x); h2_acc(a2, a3, v0.y); h2_acc(a4, a5, v0.z); h2_acc(a6, a7, v0.w);
        h2_acc(a0, a1, v1.x); h2_acc(a2, a3, v1.y); h2_acc(a4, a5, v1.z); h2_acc(a6, a7, v1.w);
        h2_acc(a0, a1, v2.x); h2_acc(a2, a3, v2.y); h2_acc(a4, a5, v2.z); h2_acc(a6, a7, v2.w);
        h2_acc(a0, a1, v3.x); h2_acc(a2, a3, v3.y); h2_acc(a4, a5, v3.z); h2_acc(a6, a7, v3.w);
    }
    for (; i < e; i++) {
        int s0 = __ldg(idx + i);
        uint4 v0 = __ldg(z + (size_t)s0 * 4 + lane);
        h2_acc(a0, a1, v0.x); h2_acc(a2, a3, v0.y); h2_acc(a4, a5, v0.z); h2_acc(a6, a7, v0.w);
    }
    uint4 o;
    o.x = pack_h2(a0, a1); o.y = pack_h2(a2, a3);
    o.z = pack_h2(a4, a5); o.w = pack_h2(a6, a7);
    __stcs(out + (size_t)r * 4 + lane, o);
}

// mode 0: hop1 (lg fp32->h4, g fp32, pmy) ; mode 1: hops 2-4 (lg h4->h4, g fp32)
__global__ void __launch_bounds__(256, 8) hops_kernel(
    const float* __restrict__ zf, const uint4* __restrict__ zh,
    const int* __restrict__ off_lg, const int* __restrict__ csr_lg, uint4* __restrict__ o_lg,
    const float* __restrict__ zg, const int* __restrict__ off_g, const int* __restrict__ csr_g,
    float* __restrict__ o_g,
    const float* __restrict__ y3, const int* __restrict__ eid3, float* __restrict__ o3, int n3,
    int mode)
{
    long long t = (long long)blockIdx.x * blockDim.x + threadIdx.x;
    int wlane = threadIdx.x & 31;
    const long long lgT = (long long)NE * 4;
    if (t < lgT) {
        int r = (int)(t >> 2), lane = (int)(t & 3);
        unsigned m4 = 0xFu << (wlane & 28);
        if (mode == 0) pull_f32_h4(zf, off_lg, csr_lg, o_lg, r, lane, m4);
        else           pull_h_h4(zh, off_lg, csr_lg, o_lg, r, lane, m4);
    } else {
        long long t2 = t - lgT;
        unsigned m8 = 0xFFu << (wlane & 24);
        if (t2 < (long long)NN * 8) {
            pull_f32_f32(zg, off_g, csr_g, o_g, (int)(t2 >> 3), (int)(t2 & 7), m8);
        } else {
            long long t3 = t2 - (long long)NN * 8;
            if (t3 < (long long)n3 * 8)
                pull_f32_f32(y3, off_g, eid3, o3, (int)(t3 >> 3), (int)(t3 & 7), m8);
        }
    }
}

// ================= fused assemble (f32x2) =================
__device__ __forceinline__ void mv_acc2(u64 acc[16], const float* __restrict__ vec,
                                        float scale, const u64 (&W)[F][16], bool streaming) {
#pragma unroll 1
    for (int k4 = 0; k4 < 8; k4++) {
        float4 v = streaming ? __ldcs((const float4*)vec + k4) : *((const float4*)vec + k4);
        float c0 = v.x * scale, c1 = v.y * scale, c2 = v.z * scale, c3 = v.w * scale;
        u64 a0 = pack2(c0, c0), a1 = pack2(c1, c1), a2 = pack2(c2, c2), a3 = pack2(c3, c3);
#pragma unroll
        for (int j = 0; j < 16; j++) acc[j] = fma2(a0, W[k4 * 4 + 0][j], acc[j]);
#pragma unroll
        for (int j = 0; j < 16; j++) acc[j] = fma2(a1, W[k4 * 4 + 1][j], acc[j]);
#pragma unroll
        for (int j = 0; j < 16; j++) acc[j] = fma2(a2, W[k4 * 4 + 2][j], acc[j]);
#pragma unroll
        for (int j = 0; j < 16; j++) acc[j] = fma2(a3, W[k4 * 4 + 3][j], acc[j]);
    }
}

__device__ __forceinline__ void mv_acc2_h(u64 acc[16], const uint4* __restrict__ vec,
                                          const u64 (&W)[F][16]) {
#pragma unroll 1
    for (int q = 0; q < 4; q++) {
        uint4 u = __ldcs(vec + q);
        float f0, f1, f2, f3, f4, f5, f6, f7;
        { __half2 h = *(__half2*)&u.x; float2 f = __half22float2(h); f0 = f.x; f1 = f.y; }
        { __half2 h = *(__half2*)&u.y; float2 f = __half22float2(h); f2 = f.x; f3 = f.y; }
        { __half2 h = *(__half2*)&u.z; float2 f = __half22float2(h); f4 = f.x; f5 = f.y; }
        { __half2 h = *(__half2*)&u.w; float2 f = __half22float2(h); f6 = f.x; f7 = f.y; }
        u64 a0 = pack2(f0, f0), a1 = pack2(f1, f1), a2 = pack2(f2, f2), a3 = pack2(f3, f3);
        u64 a4 = pack2(f4, f4), a5 = pack2(f5, f5), a6 = pack2(f6, f6), a7 = pack2(f7, f7);
        int k = q * 8;
#pragma unroll
        for (int j = 0; j < 16; j++) acc[j] = fma2(a0, W[k + 0][j], acc[j]);
#pragma unroll
        for (int j = 0; j < 16; j++) acc[j] = fma2(a1, W[k + 1][j], acc[j]);
#pragma unroll
        for (int j = 0; j < 16; j++) acc[j] = fma2(a2, W[k + 2][j], acc[j]);
#pragma unroll
        for (int j = 0; j < 16; j++) acc[j] = fma2(a3, W[k + 3][j], acc[j]);
#pragma unroll
        for (int j = 0; j < 16; j++) acc[j] = fma2(a4, W[k + 4][j], acc[j]);
#pragma unroll
        for (int j = 0; j < 16; j++) acc[j] = fma2(a5, W[k + 5][j], acc[j]);
#pragma unroll
        for (int j = 0; j < 16; j++) acc[j] = fma2(a6, W[k + 6][j], acc[j]);
#pragma unroll
        for (int j = 0; j < 16; j++) acc[j] = fma2(a7, W[k + 7][j], acc[j]);
    }
}

__global__ void assemble_both_kernel(
    const float* __restrict__ xb, const float* __restrict__ xdeg, const float* __restrict__ xextra,
    const float* __restrict__ xz0, const float* __restrict__ xz1, const float* __restrict__ xz2,
    const float* __restrict__ xWm, const float* __restrict__ xbm,
    const float* __restrict__ xWl, const float* __restrict__ xbl,
    float* __restrict__ xout, int nx, int bx,
    const float* __restrict__ yb, const float* __restrict__ ydeg, const float* __restrict__ yextra,
    const int* __restrict__ gatherIdx,
    const uint4* __restrict__ yz0, const uint4* __restrict__ yz1, const uint4* __restrict__ yz2,
    const float* __restrict__ yWm, const float* __restrict__ ybm,
    const float* __restrict__ yWl, const float* __restrict__ ybl,
    float* __restrict__ yout, int ny)
{
    bool isX = (int)blockIdx.x < bx;
    const float* Wmain = isX ? xWm : yWm;
    const float* bmain = isX ? xbm : ybm;
    const float* Wlist = isX ? xWl : yWl;
    const float* blist = isX ? xbl : ybl;

    __shared__ u64 sW[6][F][16];
    __shared__ u64 sb[16];
    for (int i = threadIdx.x; i < 6 * F * 16; i += blockDim.x) {
        int m = i >> 9;
        int rem = i & 511;
        int k = rem >> 4;
        int j2 = rem & 15;
        const float* W = (m < 3) ? (Wmain + m * 1024) : (Wlist + (m - 3) * 1024);
        sW[m][k][j2] = pack2(W[(2 * j2) * 32 + k], W[(2 * j2 + 1) * 32 + k]);
    }
    if (threadIdx.x < 16) {
        int j2 = threadIdx.x;
        float b0 = 0.f, b1 = 0.f;
#pragma unroll
        for (int m = 0; m < 3; m++) {
            b0 += bmain[m * 32 + 2 * j2] + blist[m * 32 + 2 * j2];
            b1 += bmain[m * 32 + 2 * j2 + 1] + blist[m * 32 + 2 * j2 + 1];
        }
        sb[j2] = pack2(b0, b1);
    }
    __syncthreads();

    u64 acc[16];
#pragma unroll
    for (int j = 0; j < 16; j++) acc[j] = sb[j];

    float* out;
    int r;
    if (isX) {
        r = (int)blockIdx.x * blockDim.x + threadIdx.x;
        if (r >= nx) return;
        out = xout;
        size_t r32 = (size_t)r * F;
        float dg = xdeg[r];
        mv_acc2(acc, xb + r32, 1.f, sW[0], false);
        mv_acc2(acc, xb + r32, dg,  sW[1], false);
        mv_acc2(acc, xextra + r32, 1.f, sW[2], true);
        mv_acc2(acc, xz0 + r32, 1.f, sW[3], true);
        mv_acc2(acc, xz1 + r32, 1.f, sW[4], true);
        mv_acc2(acc, xz2 + r32, 1.f, sW[5], true);
    } else {
        r = ((int)blockIdx.x - bx) * blockDim.x + threadIdx.x;
        if (r >= ny) return;
        out = yout;
        size_t r32 = (size_t)r * F;
        float dg = ydeg[r];
        mv_acc2(acc, yb + r32, 1.f, sW[0], false);
        mv_acc2(acc, yb + r32, dg,  sW[1], false);
        mv_acc2(acc, yextra + (size_t)__ldg(gatherIdx + r) * F, 1.f, sW[2], false);
        mv_acc2_h(acc, yz0 + (size_t)r * 4, sW[3]);
        mv_acc2_h(acc, yz1 + (size_t)r * 4, sW[4]);
        mv_acc2_h(acc, yz2 + (size_t)r * 4, sW[5]);
    }

    float vals[F];
#pragma unroll
    for (int j = 0; j < 16; j++) unpack2(acc[j], vals[2 * j], vals[2 * j + 1]);
#pragma unroll
    for (int j = F / 2; j < F; j++) vals[j] = fmaxf(vals[j], 0.f);

    float4* op = (float4*)(out + (size_t)r * F);
#pragma unroll
    for (int j = 0; j < 8; j++)
        op[j] = make_float4(vals[4 * j], vals[4 * j + 1], vals[4 * j + 2], vals[4 * j + 3]);
}

// ================= BN stats =================
__global__ void stats_both_kernel(const float* __restrict__ vx, const float* __restrict__ vy,
                                  int gx, float* __restrict__ st) {
    bool isX = (int)blockIdx.x < gx;
    const float* v = isX ? vx : vy;
    long long nRows = isX ? NN : NE;
    float* s0 = st + (isX ? 0 : 64);
    int nb = isX ? gx : (gridDim.x - gx);
    int rb = isX ? (int)blockIdx.x : (int)blockIdx.x - gx;

    int col = threadIdx.x & 31;
    int w = threadIdx.x >> 5;
    int warpsPerBlock = blockDim.x >> 5;
    float s = 0.f, s2 = 0.f;
    for (long long r = (long long)rb * warpsPerBlock + w; r < nRows;
         r += (long long)nb * warpsPerBlock) {
        float val = v[r * F + col];
        s += val;
        s2 += val * val;
    }
    __shared__ float sm[2][8][F];
    sm[0][w][col] = s;
    sm[1][w][col] = s2;
    __syncthreads();
    if (threadIdx.x < F) {
        float a = 0.f, b = 0.f;
#pragma unroll
        for (int ww = 0; ww < 8; ww++) { a += sm[0][ww][threadIdx.x]; b += sm[1][ww][threadIdx.x]; }
        atomicAdd(&s0[threadIdx.x], a);
        atomicAdd(&s0[F + threadIdx.x], b);
    }
}

// ================= BN normalize =================
__global__ void normalize_both_kernel(float* __restrict__ vx, float* __restrict__ vy,
                                      int gx, const float* __restrict__ st,
                                      const float* __restrict__ sx, const float* __restrict__ bxx,
                                      const float* __restrict__ sy, const float* __restrict__ byy) {
    bool isX = (int)blockIdx.x < gx;
    float* v = isX ? vx : vy;
    long long nRows = isX ? NN : NE;
    const float* s0 = st + (isX ? 0 : 64);
    const float* scale = isX ? sx : sy;
    const float* bias  = isX ? bxx : byy;
    int nb = isX ? gx : (gridDim.x - gx);
    int rb = isX ? (int)blockIdx.x : (int)blockIdx.x - gx;

    __shared__ float mulc[F], addc[F];
    if (threadIdx.x < F) {
        float m = s0[threadIdx.x] / (float)nRows;
        float var = s0[F + threadIdx.x] / (float)nRows - m * m;
        float g = rsqrtf(var + 1e-5f) * scale[threadIdx.x];
        mulc[threadIdx.x] = g;
        addc[threadIdx.x] = bias[threadIdx.x] - m * g;
    }
    __syncthreads();
    int col = threadIdx.x & 31;
    int w = threadIdx.x >> 5;
    int warpsPerBlock = blockDim.x >> 5;
    for (long long r = (long long)rb * warpsPerBlock + w; r < nRows;
         r += (long long)nb * warpsPerBlock) {
        v[r * F + col] = fmaf(v[r * F + col], mulc[col], addc[col]);
    }
}

// ================= launcher =================
extern "C" void kernel_launch(void* const* d_in, const int* in_sizes, int n_in,
                              void* d_out, int out_size) {
    const float* x            = (const float*)d_in[0];
    const float* y            = (const float*)d_in[1];
    const float* deg_g        = (const float*)d_in[2];
    const float* deg_lg       = (const float*)d_in[3];
    const float* theta_main_w = (const float*)d_in[4];
    const float* theta_main_b = (const float*)d_in[5];
    const float* theta_list_w = (const float*)d_in[6];
    const float* theta_list_b = (const float*)d_in[7];
    const float* gamma_main_w = (const float*)d_in[8];
    const float* gamma_main_b = (const float*)d_in[9];
    const float* gamma_list_w = (const float*)d_in[10];
    const float* gamma_list_b = (const float*)d_in[11];
    const float* bn_x_scale   = (const float*)d_in[12];
    const float* bn_x_bias    = (const float*)d_in[13];
    const float* bn_y_scale   = (const float*)d_in[14];
    const float* bn_y_bias    = (const float*)d_in[15];
    const int*   g_src        = (const int*)d_in[16];
    const int*   g_dst        = (const int*)d_in[17];
    const int*   lg_src       = (const int*)d_in[18];
    const int*   lg_dst       = (const int*)d_in[19];
    const int*   pm_pd        = (const int*)d_in[20];

    float* out_x = (float*)d_out;
    float* out_y = (float*)d_out + (size_t)NN * F;

    float *zg0, *zg1, *zg2, *zgt, *pmy, *st;
    uint4 *zl0, *zl1, *zl2, *zlt;
    int *cnt, *incl, *off, *rank, *csr_src_g, *csr_eid_g, *csr_lg, *bsum;
    cudaGetSymbolAddress((void**)&zg0, d_zg0);
    cudaGetSymbolAddress((void**)&zg1, d_zg1);
    cudaGetSymbolAddress((void**)&zg2, d_zg2);
    cudaGetSymbolAddress((void**)&zgt, d_zgt);
    cudaGetSymbolAddress((void**)&pmy, d_pmy);
    cudaGetSymbolAddress((void**)&zl0, d_zl0);
    cudaGetSymbolAddress((void**)&zl1, d_zl1);
    cudaGetSymbolAddress((void**)&zl2, d_zl2);
    cudaGetSymbolAddress((void**)&zlt, d_zlt);
    cudaGetSymbolAddress((void**)&st,  d_stats);
    cudaGetSymbolAddress((void**)&cnt, d_cnt);
    cudaGetSymbolAddress((void**)&incl, d_incl);
    cudaGetSymbolAddress((void**)&off, d_off);
    cudaGetSymbolAddress((void**)&rank, d_rank);
    cudaGetSymbolAddress((void**)&csr_src_g, d_csr_src_g);
    cudaGetSymbolAddress((void**)&csr_eid_g, d_csr_eid_g);
    cudaGetSymbolAddress((void**)&csr_lg, d_csr_lg);
    cudaGetSymbolAddress((void**)&bsum, d_bsum);

    int* off_g  = off;
    int* off_lg = off + NN + 1;

    const int TB = 256;
    int e4Blocks = ((NE + NLE) / 4 + TB - 1) / TB;

    // ===== CSR build =====
    hist_both_kernel<<<e4Blocks, TB>>>(g_dst, lg_dst, cnt, rank, st);
    scan_block_kernel<<<SBG + SBL, SCAN_B>>>(cnt, incl, bsum);
    scan_add_kernel<<<SBG + SBL, SCAN_B>>>(incl, cnt, bsum, off);
    fill_both_kernel<<<e4Blocks, TB>>>(g_src, g_dst, lg_src, lg_dst,
                                       off_g, off_lg, rank,
                                       csr_src_g, csr_eid_g, csr_lg);

    // ===== hops: lg 4 thr/row, g 8 thr/row =====
    long long rows1 = (long long)NE * 4 + (long long)NN * 8 + (long long)NN * 8;
    long long rows  = (long long)NE * 4 + (long long)NN * 8;
    int hBlocks1 = (int)((rows1 + TB - 1) / TB);
    int hBlocks  = (int)((rows + TB - 1) / TB);

    hops_kernel<<<hBlocks1, TB>>>(y, nullptr, off_lg, csr_lg, zl0,
                                  x, off_g, csr_src_g, zg0,
                                  y, csr_eid_g, pmy, NN, 0);
    hops_kernel<<<hBlocks, TB>>>(nullptr, zl0, off_lg, csr_lg, zl1,
                                 zg0, off_g, csr_src_g, zg1,
                                 nullptr, nullptr, nullptr, 0, 1);
    hops_kernel<<<hBlocks, TB>>>(nullptr, zl1, off_lg, csr_lg, zlt,
                                 zg1, off_g, csr_src_g, zgt,
                                 nullptr, nullptr, nullptr, 0, 1);
    hops_kernel<<<hBlocks, TB>>>(nullptr, zlt, off_lg, csr_lg, zl2,
                                 zgt, off_g, csr_src_g, zg2,
                                 nullptr, nullptr, nullptr, 0, 1);

    // ===== assemble =====
    int bx = (NN + TB - 1) / TB;
    int by = (NE + TB - 1) / TB;
    assemble_both_kernel<<<bx + by, TB>>>(
        x, deg_g, pmy, zg0, zg1, zg2,
        theta_main_w, theta_main_b, theta_list_w, theta_list_b, out_x, NN, bx,
        y, deg_lg, x, pm_pd, zl0, zl1, zl2,
        gamma_main_w, gamma_main_b, gamma_list_w, gamma_list_b, out_y, NE);

    // ===== batchnorm =====
    stats_both_kernel<<<512 + 2048, TB>>>(out_x, out_y, 512, st);
    normalize_both_kernel<<<512 + 2048, TB>>>(out_x, out_y, 512, st,
                                              bn_x_scale, bn_x_bias, bn_y_scale, bn_y_bias);
}